// round 9
// baseline (speedup 1.0000x reference)
#include <cuda_runtime.h>
#include <math.h>

// ---------------- problem constants ----------------
#define T_STEPS 512
#define BATCH   128
#define HDIM    300
#define MCELLS  20
#define ROWS    (BATCH*MCELLS)   // 2560
#define DECAY   0.98f
#define EPS_V   1e-8f

#define NTHREADS 256
#define NJOBS    1260  // (3 matrices * 40rt*5ct + P 2rt*15ct) * 2 K-halves
#define RH       (ROWS*HDIM)
#define PSZ      (BATCH*900)
#define KHALF    152           // padded K half (2*152 = 304 >= 300)
#define NSTAGE   19            // 152/8

// 1 = JAX >= 0.4.30 default (threefry_partitionable)
#define THREEFRY_PARTITIONABLE 1

// ---------------- device state (no allocation anywhere) ----------------
__device__ float g_mem[RH];             // (B,M,H)
__device__ float g_usage[ROWS];         // (B,M)
__device__ float g_HPa [RH];            // mem@Ws1[0:300], K half 0
__device__ float g_HPb [RH];            // K half 1
__device__ float g_HP2a[RH];            // (h*mem)@Ws1[600:900] halves
__device__ float g_HP2b[RH];
__device__ float g_CPa [RH];            // mem@Wu[300:600] halves
__device__ float g_CPb [RH];
__device__ float g_Pa[PSZ];             // h@[We1|Ws1(300:600)|Wu(0:300)] halves
__device__ float g_Pb[PSZ];
__device__ float g_cand[RH];            // tanh(CPa+CPb + P6 + bu)
__device__ float g_ow[ROWS];
__device__ float g_indv[ROWS];
__device__ unsigned g_count;            // grid-barrier counter
__device__ unsigned g_jobctr[T_STEPS];  // per-step dynamic job counters

// ---------------- software grid barrier ----------------
__device__ __forceinline__ void grid_bar(unsigned &target, int nblk) {
    __syncthreads();
    if (threadIdx.x == 0) {
        target += (unsigned)nblk;
        __threadfence();
        atomicAdd(&g_count, 1u);
        volatile unsigned* p = &g_count;
        while (*p < target) { }
        __threadfence();
    }
    __syncthreads();
}

// ---------------- JAX threefry-2x32-20 noise ----------------
__device__ __forceinline__ void tf_round(unsigned &x0, unsigned &x1, int r) {
    x0 += x1;
    x1 = (x1 << r) | (x1 >> (32 - r));
    x1 ^= x0;
}
__device__ __forceinline__ void threefry2x32(unsigned c0, unsigned c1,
                                             unsigned &o0, unsigned &o1) {
    const unsigned k0 = 0u, k1 = 42u, k2 = 0x1BD11BDAu ^ 0u ^ 42u;
    unsigned x0 = c0 + k0, x1 = c1 + k1;
    tf_round(x0,x1,13); tf_round(x0,x1,15); tf_round(x0,x1,26); tf_round(x0,x1,6);
    x0 += k1; x1 += k2 + 1u;
    tf_round(x0,x1,17); tf_round(x0,x1,29); tf_round(x0,x1,16); tf_round(x0,x1,24);
    x0 += k2; x1 += k0 + 2u;
    tf_round(x0,x1,13); tf_round(x0,x1,15); tf_round(x0,x1,26); tf_round(x0,x1,6);
    x0 += k0; x1 += k1 + 3u;
    tf_round(x0,x1,17); tf_round(x0,x1,29); tf_round(x0,x1,16); tf_round(x0,x1,24);
    x0 += k1; x1 += k2 + 4u;
    tf_round(x0,x1,13); tf_round(x0,x1,15); tf_round(x0,x1,26); tf_round(x0,x1,6);
    x0 += k2; x1 += k0 + 5u;
    o0 = x0; o1 = x1;
}
__device__ __forceinline__ float jax_noise(unsigned i) {
    unsigned bits;
#if THREEFRY_PARTITIONABLE
    unsigned o0, o1;
    threefry2x32(0u, i, o0, o1);
    bits = o0 ^ o1;
#else
    const unsigned half = (unsigned)(T_STEPS*BATCH*MCELLS) / 2u;
    unsigned o0, o1;
    if (i < half) { threefry2x32(i, i + half, o0, o1); bits = o0; }
    else          { threefry2x32(i - half, i, o0, o1); bits = o1; }
#endif
    float f = __uint_as_float((bits >> 9) | 0x3f800000u) - 1.0f;
    float u = __fadd_rn(__fmul_rn(f, 0.99f), 0.01f);
    return fmaxf(0.01f, u);
}

// ---------------- warp reductions ----------------
__device__ __forceinline__ float warpSum(float v) {
#pragma unroll
    for (int o = 16; o; o >>= 1) v += __shfl_xor_sync(0xffffffffu, v, o);
    return v;
}
__device__ __forceinline__ float warpMax(float v) {
#pragma unroll
    for (int o = 16; o; o >>= 1) v = fmaxf(v, __shfl_xor_sync(0xffffffffu, v, o));
    return v;
}

// fast tanh: abs err ~1e-6; __expf(inf)->inf gives exact saturation
__device__ __forceinline__ float tanh_fast(float x) {
    float ax = fabsf(x);
    float e  = __expf(2.0f * ax);
    float r  = 1.0f - __fdividef(2.0f, e + 1.0f);
    return copysignf(r, x);
}

// ---------------- tf32 helpers ----------------
__device__ __forceinline__ unsigned f2tf32(float x) {
    unsigned u;
    asm("cvt.rna.tf32.f32 %0, %1;" : "=r"(u) : "f"(x));
    return u;
}
__device__ __forceinline__ void split_tf32(float x, unsigned &big, unsigned &small) {
    big = f2tf32(x);
    float rem = x - __uint_as_float(big);
    small = f2tf32(rem);
}
__device__ __forceinline__ void mma_tf32(float c[4],
    unsigned a0, unsigned a1, unsigned a2, unsigned a3,
    unsigned b0, unsigned b1)
{
    asm("mma.sync.aligned.m16n8k8.row.col.f32.tf32.tf32.f32 "
        "{%0,%1,%2,%3}, {%4,%5,%6,%7}, {%8,%9}, {%0,%1,%2,%3};"
        : "+f"(c[0]), "+f"(c[1]), "+f"(c[2]), "+f"(c[3])
        : "r"(a0), "r"(a1), "r"(a2), "r"(a3), "r"(b0), "r"(b1));
}

// ---------------- GEMM tile job (tensor cores, 3xTF32) ----------------
// 1260 jobs. job<1200: mtype=job/400 (0=HP 1=HP2 2=CP), e=job%400, kh=e&1,
//   e2=e>>1: r0=(e2/5)*64 (2560 rows), c0=(e2%5)*64 (300 cols).
// job>=1200: P: e=job-1200, kh=e&1, e2=e>>1: r0=(e2/15)*64 (128 rows),
//   c0=(e2%15)*64 (900 cols).
// K-half: kstart = kh*152, 19 k8-stages; kg >= 300 zero-padded.
#define BM 64
#define BN 64

__device__ __forceinline__ void gemm_job(
    int job, int t,
    const float* __restrict__ hs, const float* __restrict__ We1,
    const float* __restrict__ Ws1, const float* __restrict__ Wu,
    float (&As)[2][8][68], float (&Bs)[2][8][68])
{
    const int tid = threadIdx.x;
    const float* hbase = hs + (size_t)t * BATCH * HDIM;

    int mtype, r0, c0, kh, ncols;
    if (job < 1200) {
        mtype = job / 400;
        int e = job % 400;  kh = e & 1;  int e2 = e >> 1;
        r0 = (e2 / 5) * BM;  c0 = (e2 % 5) * BN;  ncols = 300;
    } else {
        mtype = 3;
        int e = job - 1200; kh = e & 1;  int e2 = e >> 1;
        r0 = (e2 / 15) * BM; c0 = (e2 % 15) * BN; ncols = 900;
    }
    const int kstart = kh * KHALF;

    // ---- hoisted gmem load coordinates ----
    // A: thread loads elems (m=tid>>3, k=tid&7) and (m+32, k) of the 64x8 tile
    const int am = tid >> 3, ak = tid & 7;
    const int rg0 = r0 + am, rg1 = r0 + am + 32;
    const float* aSrc = (mtype == 3) ? hbase : g_mem;
    const float* aRow0 = aSrc + rg0*HDIM;
    const float* aRow1 = aSrc + rg1*HDIM;
    const float* hRow0 = hbase + (rg0/MCELLS)*HDIM;
    const float* hRow1 = hbase + (rg1/MCELLS)*HDIM;
    // B: thread loads elems (k=tid>>6, n=tid&63) and (k+4, n) of the 8x64 tile
    const int bn = tid & 63, bk0 = tid >> 6, bk1 = bk0 + 4;
    const int jg = c0 + bn;
    const bool bok = (jg < ncols);
    const float* bp = Ws1;   // safe dummy
    if (bok) {
        if (mtype == 0)      bp = Ws1 + jg;
        else if (mtype == 1) bp = Ws1 + 600*300 + jg;
        else if (mtype == 2) bp = Wu  + 300*300 + jg;
        else {
            int role = jg / 300, jc = jg - role*300;
            if (role == 0)      bp = We1 + jc;
            else if (role == 1) bp = Ws1 + 300*300 + jc;
            else                bp = Wu  + jc;
        }
    }

    // ---- warp tile coordinates: 8 warps -> 2(m) x 4(n); warp tile 32x16 ----
    const int warp = tid >> 5, lane = tid & 31;
    const int m0 = (warp >> 2) * 32;
    const int n0 = (warp & 3) * 16;
    const int lg = lane >> 2, lt = lane & 3;

    float c[2][2][4];
#pragma unroll
    for (int i = 0; i < 2; i++)
#pragma unroll
        for (int j = 0; j < 2; j++)
#pragma unroll
            for (int q = 0; q < 4; q++) c[i][j][q] = 0.f;

    float sa0, sa1, sb0, sb1;   // staging regs
    auto ldStage = [&](int s) {
        int kg = kstart + s*8 + ak;
        bool ok = (kg < 300);
        float v0 = ok ? aRow0[kg] : 0.f;
        float v1 = ok ? aRow1[kg] : 0.f;
        if (mtype == 1 && ok) { v0 *= hRow0[kg]; v1 *= hRow1[kg]; }
        sa0 = v0; sa1 = v1;
        int kg0 = kstart + s*8 + bk0;
        int kg1 = kstart + s*8 + bk1;
        sb0 = (bok && kg0 < 300) ? bp[kg0*300] : 0.f;
        sb1 = (bok && kg1 < 300) ? bp[kg1*300] : 0.f;
    };
    auto stStage = [&](int buf) {
        As[buf][ak][am]      = sa0;
        As[buf][ak][am + 32] = sa1;
        Bs[buf][bk0][bn]     = sb0;
        Bs[buf][bk1][bn]     = sb1;
    };

    ldStage(0);
    stStage(0);
    __syncthreads();

    for (int s = 0; s < NSTAGE; s++) {
        int cur = s & 1;
        if (s + 1 < NSTAGE) ldStage(s + 1);

        // load + split fragments
        unsigned Ab[2][4], Asm[2][4], Bb[2][2], Bsm[2][2];
#pragma unroll
        for (int mi = 0; mi < 2; mi++) {
            int mb = m0 + mi*16;
            float f0 = As[cur][lt]  [mb + lg];
            float f1 = As[cur][lt]  [mb + lg + 8];
            float f2 = As[cur][lt+4][mb + lg];
            float f3 = As[cur][lt+4][mb + lg + 8];
            split_tf32(f0, Ab[mi][0], Asm[mi][0]);
            split_tf32(f1, Ab[mi][1], Asm[mi][1]);
            split_tf32(f2, Ab[mi][2], Asm[mi][2]);
            split_tf32(f3, Ab[mi][3], Asm[mi][3]);
        }
#pragma unroll
        for (int ni = 0; ni < 2; ni++) {
            int nb = n0 + ni*8;
            float g0 = Bs[cur][lt]  [nb + lg];
            float g1 = Bs[cur][lt+4][nb + lg];
            split_tf32(g0, Bb[ni][0], Bsm[ni][0]);
            split_tf32(g1, Bb[ni][1], Bsm[ni][1]);
        }
#pragma unroll
        for (int mi = 0; mi < 2; mi++)
#pragma unroll
            for (int ni = 0; ni < 2; ni++) {
                mma_tf32(c[mi][ni], Asm[mi][0], Asm[mi][1], Asm[mi][2], Asm[mi][3],
                         Bb[ni][0], Bb[ni][1]);
                mma_tf32(c[mi][ni], Ab[mi][0], Ab[mi][1], Ab[mi][2], Ab[mi][3],
                         Bsm[ni][0], Bsm[ni][1]);
                mma_tf32(c[mi][ni], Ab[mi][0], Ab[mi][1], Ab[mi][2], Ab[mi][3],
                         Bb[ni][0], Bb[ni][1]);
            }

        if (s + 1 < NSTAGE) stStage(cur ^ 1);
        __syncthreads();
    }

    float* dst;
    if (mtype == 0)      dst = kh ? g_HPb  : g_HPa;
    else if (mtype == 1) dst = kh ? g_HP2b : g_HP2a;
    else if (mtype == 2) dst = kh ? g_CPb  : g_CPa;
    else                 dst = kh ? g_Pb   : g_Pa;

#pragma unroll
    for (int mi = 0; mi < 2; mi++)
#pragma unroll
        for (int ni = 0; ni < 2; ni++) {
            int row = r0 + m0 + mi*16 + lg;
            int col = c0 + n0 + ni*8 + 2*lt;
            if (col < ncols) {
                dst[row*ncols + col]       = c[mi][ni][0];
                dst[(row+8)*ncols + col]   = c[mi][ni][2];
            }
            if (col + 1 < ncols) {
                dst[row*ncols + col + 1]     = c[mi][ni][1];
                dst[(row+8)*ncols + col + 1] = c[mi][ni][3];
            }
        }
}

// ---------------- gating job (block handles batch b) ----------------
__device__ __forceinline__ void gate_job(
    int b, int t,
    const float* __restrict__ mask,
    const float* __restrict__ be1, const float* __restrict__ We2,
    const float* __restrict__ be2, const float* __restrict__ bs1,
    const float* __restrict__ Ws2, const float* __restrict__ bs2,
    const float* __restrict__ Ws1,
    float* __restrict__ out,
    float (&s_sim)[MCELLS], float (&s_usage)[MCELLS],
    float (&s_red)[8], float &s_ent)
{
    const int tid = threadIdx.x;
    const int warp = tid >> 5, lane = tid & 31;

    const float* Pa = g_Pa + b*900;
    const float* Pb = g_Pb + b*900;
    const float* wu_row = Ws1 + 900*300;

    if (tid < MCELLS) s_usage[tid] = g_usage[b*MCELLS + tid];
    __syncthreads();

    // ---- entity prob ----
    float acc = 0.f;
    for (int j = tid; j < 300; j += NTHREADS)
        acc += fmaxf(Pa[j] + Pb[j] + be1[j], 0.f) * We2[j];
    acc = warpSum(acc);
    if (lane == 0) s_red[warp] = acc;
    __syncthreads();
    if (tid == 0) {
        float s = 0.f;
        for (int w = 0; w < 8; w++) s += s_red[w];
        float score = s + be2[0];
        float sig = 1.f / (1.f + expf(-score));
        s_ent = sig * mask[(size_t)t*BATCH + b];
    }

    // ---- sim[m] ----
    for (int m = warp; m < MCELLS; m += 8) {
        float u = s_usage[m];
        const int ro = (b*MCELLS + m)*300;
        float a = 0.f;
        for (int j = lane; j < 300; j += 32) {
            float pre = g_HPa[ro+j] + g_HPb[ro+j] + g_HP2a[ro+j] + g_HP2b[ro+j]
                      + Pa[300 + j] + Pb[300 + j] + u*wu_row[j] + bs1[j];
            a += fmaxf(pre, 0.f) * Ws2[j];
        }
        a = warpSum(a);
        if (lane == 0) s_sim[m] = a + bs2[0];
    }
    __syncthreads();

    // ---- gating (warp 0; lane = slot 0..20) ----
    if (warp == 0) {
        const unsigned FULL = 0xffffffffu;
        const int m = lane;
        const float NEG_INF = -INFINITY;
        float usg  = (m < MCELLS) ? s_usage[m] : 0.f;
        float simv = (m < MCELLS) ? s_sim[m]   : 0.f;

        float comb;
        if (m < MCELLS)       comb = (usg > 0.f) ? simv : -10000.f;
        else if (m == MCELLS) comb = 0.f;
        else                  comb = NEG_INF;
        float mx   = warpMax(comb);
        float ex   = (m <= MCELLS) ? expf(comb - mx) : 0.f;
        float esum = warpSum(ex);
        float prob = ex / esum;
        float mult = (m < MCELLS) ? ((usg > 0.f) ? 1.f : 0.f)
                                  : ((m == MCELLS) ? 1.f : 0.f);
        float maskedp = prob * mult;
        float msum = warpSum(maskedp);
        float nrm  = maskedp / (msum + EPS_V);
        float co   = s_ent * nrm;
        float ow_base = __shfl_sync(FULL, co, MCELLS);
        float indv = (m < MCELLS) ? co : 0.f;

        float s2  = (m < MCELLS) ? simv : NEG_INF;
        float mx2 = warpMax(s2);
        float e2  = (m < MCELLS) ? expf(simv - mx2) : 0.f;
        float es2 = warpSum(e2);
        float nsim = e2 / es2;

        float ow_score = (m < MCELLS)
            ? ((usg == 0.f ? nsim * 100000.f : 0.f) + (1.f - usg))
            : NEG_INF;
        float maxv = warpMax(ow_score);
        float nz   = (m < MCELLS && ow_score == maxv)
            ? jax_noise((unsigned)(((size_t)t*BATCH + b)*MCELLS + m)) : 0.f;
        float nzmax = warpMax(nz);
        unsigned ballot = __ballot_sync(FULL, (m < MCELLS) && (nz == nzmax));
        int idx = __ffs(ballot) - 1;

        float ow = (m == idx) ? ow_base : 0.f;
        float nu = fminf(1.f, ow + indv + DECAY * usg);

        float* out_ent = out;
        float* out_usg = out + (size_t)T_STEPS*BATCH;
        float* out_crf = out_usg + (size_t)T_STEPS*BATCH*MCELLS;
        float* out_ow  = out_crf + (size_t)T_STEPS*BATCH*MCELLS;
        if (m < MCELLS) {
            g_ow[b*MCELLS + m]    = ow;
            g_indv[b*MCELLS + m]  = indv;
            g_usage[b*MCELLS + m] = nu;
            size_t o = ((size_t)t*BATCH + b)*MCELLS + m;
            out_usg[o] = nu;
            out_crf[o] = indv * (1.f - EPS_V) + EPS_V;
            out_ow[o]  = ow   * (1.f - EPS_V) + EPS_V;
        }
        if (m == 0)
            out_ent[(size_t)t*BATCH + b] = s_ent * (1.f - EPS_V) + EPS_V;
    }
}

// ---------------- persistent kernel ----------------
__global__ __launch_bounds__(NTHREADS, 2) void k_persist(
    const float* __restrict__ hs, const float* __restrict__ mask,
    const float* __restrict__ We1, const float* __restrict__ be1,
    const float* __restrict__ We2, const float* __restrict__ be2,
    const float* __restrict__ Ws1, const float* __restrict__ bs1,
    const float* __restrict__ Ws2, const float* __restrict__ bs2,
    const float* __restrict__ Wu,  const float* __restrict__ bu,
    float* __restrict__ out, int nblk)
{
    __shared__ float As[2][8][68];
    __shared__ float Bs[2][8][68];
    __shared__ float s_sim[MCELLS], s_usage[MCELLS];
    __shared__ float s_red[8];
    __shared__ float s_ent;
    __shared__ int s_job;

    const int tid = threadIdx.x;
    unsigned target = 0;

    for (int t = 0; t < T_STEPS; t++) {
        // ---- phase A: GEMMs (dynamic, tensor cores) ----
        for (;;) {
            if (tid == 0) s_job = (int)atomicAdd(&g_jobctr[t], 1u);
            __syncthreads();
            int job = s_job;
            __syncthreads();
            if (job >= NJOBS) break;
            gemm_job(job, t, hs, We1, Ws1, Wu, As, Bs);
        }
        grid_bar(target, nblk);

        // ---- phase B: gate (blocks 0..127) || cand precompute (rest) ----
        if (blockIdx.x < BATCH) {
            gate_job(blockIdx.x, t, mask, be1, We2, be2, bs1, Ws2, bs2,
                     Ws1, out, s_sim, s_usage, s_red, s_ent);
        } else {
            const float4* CPa4 = (const float4*)g_CPa;
            const float4* CPb4 = (const float4*)g_CPb;
            const float4* Pa4  = (const float4*)g_Pa;
            const float4* Pb4  = (const float4*)g_Pb;
            const float4* bu4  = (const float4*)bu;
            float4* cand4 = (float4*)g_cand;
            const int total = ROWS * 75;
            const int nb = nblk - BATCH;
            for (int idx = (blockIdx.x - BATCH)*NTHREADS + tid; idx < total;
                 idx += nb*NTHREADS) {
                int r  = idx / 75;
                int jq = idx - r*75;
                int b  = r / MCELLS;
                float4 ca = CPa4[idx], cb = CPb4[idx];
                int pbase = b*225 + 150 + jq;
                float4 pa = Pa4[pbase], pb = Pb4[pbase];
                float4 bv = bu4[jq];
                float4 res;
                res.x = tanh_fast(ca.x + cb.x + pa.x + pb.x + bv.x);
                res.y = tanh_fast(ca.y + cb.y + pa.y + pb.y + bv.y);
                res.z = tanh_fast(ca.z + cb.z + pa.z + pb.z + bv.z);
                res.w = tanh_fast(ca.w + cb.w + pa.w + pb.w + bv.w);
                cand4[idx] = res;
            }
        }
        grid_bar(target, nblk);

        // ---- phase C: mem update (all blocks, float4) ----
        {
            const float4* hb4 = (const float4*)(hs + (size_t)t*BATCH*HDIM);
            const float4* cand4 = (const float4*)g_cand;
            float4* mem4 = (float4*)g_mem;
            const int total = ROWS * 75;
            for (int idx = blockIdx.x*NTHREADS + tid; idx < total;
                 idx += nblk*NTHREADS) {
                int r  = idx / 75;
                int jq = idx - r*75;
                int b  = r / MCELLS;
                float owv = g_ow[r], iv = g_indv[r];
                float coef = 1.f - owv - iv;
                float4 cd = cand4[idx];
                float4 h  = hb4[b*75 + jq];
                float4 mo = mem4[idx];
                float4 res;
                res.x = owv*h.x + coef*mo.x + iv*cd.x;
                res.y = owv*h.y + coef*mo.y + iv*cd.y;
                res.z = owv*h.z + coef*mo.z + iv*cd.z;
                res.w = owv*h.w + coef*mo.w + iv*cd.w;
                mem4[idx] = res;
            }
        }
        grid_bar(target, nblk);
    }
}

extern "C" void kernel_launch(void* const* d_in, const int* in_sizes, int n_in,
                              void* d_out, int out_size) {
    const float* hs   = (const float*)d_in[0];
    const float* mask = (const float*)d_in[1];
    const float* We1  = (const float*)d_in[2];
    const float* be1  = (const float*)d_in[3];
    const float* We2  = (const float*)d_in[4];
    const float* be2  = (const float*)d_in[5];
    const float* Ws1  = (const float*)d_in[6];
    const float* bs1  = (const float*)d_in[7];
    const float* Ws2  = (const float*)d_in[8];
    const float* bs2  = (const float*)d_in[9];
    const float* Wu   = (const float*)d_in[10];
    const float* bu   = (const float*)d_in[11];
    float* out = (float*)d_out;

    int smcount = 148;
    cudaDeviceGetAttribute(&smcount, cudaDevAttrMultiProcessorCount, 0);
    int nblk = 2 * smcount;

    void *pmem, *pusg, *pcnt, *pjob;
    cudaGetSymbolAddress(&pmem, g_mem);
    cudaGetSymbolAddress(&pusg, g_usage);
    cudaGetSymbolAddress(&pcnt, g_count);
    cudaGetSymbolAddress(&pjob, g_jobctr);
    cudaMemsetAsync(pmem, 0, sizeof(float)*(size_t)RH);
    cudaMemsetAsync(pusg, 0, sizeof(float)*(size_t)ROWS);
    cudaMemsetAsync(pcnt, 0, sizeof(unsigned));
    cudaMemsetAsync(pjob, 0, sizeof(unsigned)*T_STEPS);

    k_persist<<<nblk, NTHREADS>>>(hs, mask, We1, be1, We2, be2,
                                  Ws1, bs1, Ws2, bs2, Wu, bu, out, nblk);
}

// round 10
// speedup vs baseline: 1.1353x; 1.1353x over previous
#include <cuda_runtime.h>
#include <math.h>

// ---------------- problem constants ----------------
#define T_STEPS 512
#define BATCH   128
#define HDIM    300
#define MCELLS  20
#define ROWS    (BATCH*MCELLS)   // 2560
#define DECAY   0.98f
#define EPS_V   1e-8f

#define NTHREADS 256
#define NJOBS    1260   // (3 matrices * 20rt*5ct + P 15ct) * 4 K-quarters
#define RH       (ROWS*HDIM)
#define PSZ      (BATCH*900)
#define KQ       80     // K-quarter span (4*80 = 320 >= 300, padded)
#define NSTAGE   5      // 80/16
#define WBTOT    540000 // precomputed weight-split table entries

// 1 = JAX >= 0.4.30 default (threefry_partitionable)
#define THREEFRY_PARTITIONABLE 1

// ---------------- device state (no allocation anywhere) ----------------
__device__ float g_mem[RH];             // (B,M,H)
__device__ float g_usage[ROWS];         // (B,M)
__device__ float g_HP [4*RH];           // mem@Ws1[0:300]       per K-quarter
__device__ float g_HP2[4*RH];           // (h*mem)@Ws1[600:900] per K-quarter
__device__ float g_CP [4*RH];           // mem@Wu[300:600]      per K-quarter
__device__ float g_P  [4*PSZ];          // h@[We1|Ws1mid|Wu0]   per K-quarter
__device__ float g_cand[RH];            // tanh(sum CP + P6 + bu)
__device__ float g_ow[ROWS];
__device__ float g_indv[ROWS];
__device__ uint2 g_WB[WBTOT];           // weight tf32 splits {big,small}
__device__ unsigned g_count;            // grid-barrier counter
__device__ unsigned g_jobctr[T_STEPS];  // per-step dynamic job counters

// ---------------- software grid barrier ----------------
__device__ __forceinline__ void grid_bar(unsigned &target, int nblk) {
    __syncthreads();
    if (threadIdx.x == 0) {
        target += (unsigned)nblk;
        __threadfence();
        atomicAdd(&g_count, 1u);
        volatile unsigned* p = &g_count;
        while (*p < target) { }
        __threadfence();
    }
    __syncthreads();
}

// ---------------- JAX threefry-2x32-20 noise ----------------
__device__ __forceinline__ void tf_round(unsigned &x0, unsigned &x1, int r) {
    x0 += x1;
    x1 = (x1 << r) | (x1 >> (32 - r));
    x1 ^= x0;
}
__device__ __forceinline__ void threefry2x32(unsigned c0, unsigned c1,
                                             unsigned &o0, unsigned &o1) {
    const unsigned k0 = 0u, k1 = 42u, k2 = 0x1BD11BDAu ^ 0u ^ 42u;
    unsigned x0 = c0 + k0, x1 = c1 + k1;
    tf_round(x0,x1,13); tf_round(x0,x1,15); tf_round(x0,x1,26); tf_round(x0,x1,6);
    x0 += k1; x1 += k2 + 1u;
    tf_round(x0,x1,17); tf_round(x0,x1,29); tf_round(x0,x1,16); tf_round(x0,x1,24);
    x0 += k2; x1 += k0 + 2u;
    tf_round(x0,x1,13); tf_round(x0,x1,15); tf_round(x0,x1,26); tf_round(x0,x1,6);
    x0 += k0; x1 += k1 + 3u;
    tf_round(x0,x1,17); tf_round(x0,x1,29); tf_round(x0,x1,16); tf_round(x0,x1,24);
    x0 += k1; x1 += k2 + 4u;
    tf_round(x0,x1,13); tf_round(x0,x1,15); tf_round(x0,x1,26); tf_round(x0,x1,6);
    x0 += k2; x1 += k0 + 5u;
    o0 = x0; o1 = x1;
}
__device__ __forceinline__ float jax_noise(unsigned i) {
    unsigned bits;
#if THREEFRY_PARTITIONABLE
    unsigned o0, o1;
    threefry2x32(0u, i, o0, o1);
    bits = o0 ^ o1;
#else
    const unsigned half = (unsigned)(T_STEPS*BATCH*MCELLS) / 2u;
    unsigned o0, o1;
    if (i < half) { threefry2x32(i, i + half, o0, o1); bits = o0; }
    else          { threefry2x32(i - half, i, o0, o1); bits = o1; }
#endif
    float f = __uint_as_float((bits >> 9) | 0x3f800000u) - 1.0f;
    float u = __fadd_rn(__fmul_rn(f, 0.99f), 0.01f);
    return fmaxf(0.01f, u);
}

// ---------------- warp reductions ----------------
__device__ __forceinline__ float warpSum(float v) {
#pragma unroll
    for (int o = 16; o; o >>= 1) v += __shfl_xor_sync(0xffffffffu, v, o);
    return v;
}
__device__ __forceinline__ float warpMax(float v) {
#pragma unroll
    for (int o = 16; o; o >>= 1) v = fmaxf(v, __shfl_xor_sync(0xffffffffu, v, o));
    return v;
}

// fast tanh: abs err ~1e-6; __expf(inf)->inf gives exact saturation
__device__ __forceinline__ float tanh_fast(float x) {
    float ax = fabsf(x);
    float e  = __expf(2.0f * ax);
    float r  = 1.0f - __fdividef(2.0f, e + 1.0f);
    return copysignf(r, x);
}

// ---------------- tf32 helpers ----------------
__device__ __forceinline__ unsigned f2tf32(float x) {
    unsigned u;
    asm("cvt.rna.tf32.f32 %0, %1;" : "=r"(u) : "f"(x));
    return u;
}
__device__ __forceinline__ void split_tf32(float x, unsigned &big, unsigned &small) {
    big = f2tf32(x);
    float rem = x - __uint_as_float(big);
    small = f2tf32(rem);
}
__device__ __forceinline__ void mma_tf32(float c[4],
    unsigned a0, unsigned a1, unsigned a2, unsigned a3,
    unsigned b0, unsigned b1)
{
    asm("mma.sync.aligned.m16n8k8.row.col.f32.tf32.tf32.f32 "
        "{%0,%1,%2,%3}, {%4,%5,%6,%7}, {%8,%9}, {%0,%1,%2,%3};"
        : "+f"(c[0]), "+f"(c[1]), "+f"(c[2]), "+f"(c[3])
        : "r"(a0), "r"(a1), "r"(a2), "r"(a3), "r"(b0), "r"(b1));
}

// ---------------- GEMM tile job (tensor cores, 3xTF32, BM=128/BN=64/BK=16) ----
// 1260 jobs. job<1200: mtype=job/400 (0=HP 1=HP2 2=CP), e=job%400, kq=e&3,
//   e2=e>>2: r0=(e2/5)*128 (2560 rows), c0=(e2%5)*64 (300 cols).
// job>=1200: P: e=job-1200, kq=e&3, c0=(e>>2)*64 (900 cols), r0=0.
// K-quarter: kstart = kq*80, 5 k16-stages; kg >= 300 zero-padded.
__device__ __forceinline__ void gemm_job(
    int job, int t,
    const float* __restrict__ hs,
    uint2 (&SA)[16][130], uint2 (&SB)[16][66])
{
    const int tid = threadIdx.x;
    const float* hbase = hs + (size_t)t * BATCH * HDIM;

    int mtype, r0, c0, kq, ncols, wboff, wstride;
    if (job < 1200) {
        mtype = job / 400;
        int e = job % 400;  kq = e & 3;  int e2 = e >> 2;
        r0 = (e2 / 5) * 128;  c0 = (e2 % 5) * 64;  ncols = 300;
        wboff = mtype * 90000; wstride = 300;
    } else {
        mtype = 3;
        int e = job - 1200; kq = e & 3;
        r0 = 0;  c0 = (e >> 2) * 64;  ncols = 900;
        wboff = 270000; wstride = 900;
    }
    const int kstart = kq * KQ;

    // ---- A staging coords: 8 elems, m = (tid>>4)+i*16, k = tid&15 ----
    const int am = tid >> 4, ak = tid & 15;
    const float* aSrc = (mtype == 3) ? hbase : g_mem;
    const float* aBase = aSrc + (r0 + am) * HDIM;   // + i*16*HDIM
    int hOff[8];
#pragma unroll
    for (int i = 0; i < 8; i++)
        hOff[i] = ((r0 + am + i*16) / MCELLS) * HDIM;

    // ---- B staging coords: 4 uint2, n = tid&63, k = (tid>>6)+i*4 ----
    const int bn = tid & 63, bk = tid >> 6;
    const bool bok = (c0 + bn) < ncols;
    const uint2* wb = g_WB + wboff + (c0 + bn);

    // ---- warp tile: 8 warps = 4m x 2n, warp tile 32x32 ----
    const int warp = tid >> 5, lane = tid & 31;
    const int m0 = (warp >> 1) * 32;
    const int n0 = (warp & 1) * 32;
    const int lg = lane >> 2, lt = lane & 3;

    float c[2][4][4];
#pragma unroll
    for (int mi = 0; mi < 2; mi++)
#pragma unroll
        for (int ni = 0; ni < 4; ni++)
#pragma unroll
            for (int q = 0; q < 4; q++) c[mi][ni][q] = 0.f;

    float ra[8];
    uint2 rb[4];
    auto ldStage = [&](int s) {
        int kg = kstart + s*16 + ak;
        bool ok = (kg < 300);
#pragma unroll
        for (int i = 0; i < 8; i++)
            ra[i] = ok ? aBase[i*16*HDIM + kg] : 0.f;
        if (mtype == 1 && ok) {
#pragma unroll
            for (int i = 0; i < 8; i++)
                ra[i] *= hbase[hOff[i] + kg];
        }
#pragma unroll
        for (int i = 0; i < 4; i++) {
            int kg2 = kstart + s*16 + bk + i*4;
            rb[i] = (bok && kg2 < 300) ? wb[kg2*wstride] : make_uint2(0u, 0u);
        }
    };
    auto stStage = [&]() {
#pragma unroll
        for (int i = 0; i < 8; i++) {
            uint2 v;
            split_tf32(ra[i], v.x, v.y);
            SA[ak][am + i*16] = v;
        }
#pragma unroll
        for (int i = 0; i < 4; i++)
            SB[bk + i*4][bn] = rb[i];
    };

    ldStage(0);
    stStage();
    __syncthreads();

    for (int s = 0; s < NSTAGE; s++) {
        if (s + 1 < NSTAGE) ldStage(s + 1);   // prefetch into regs
#pragma unroll
        for (int kk = 0; kk < 2; kk++) {
            const int kb = kk * 8;
            unsigned Ab[2][4], Asm[2][4];
#pragma unroll
            for (int mi = 0; mi < 2; mi++) {
                int mb = m0 + mi*16;
                uint2 v0 = SA[kb + lt]    [mb + lg];
                uint2 v1 = SA[kb + lt]    [mb + lg + 8];
                uint2 v2 = SA[kb + lt + 4][mb + lg];
                uint2 v3 = SA[kb + lt + 4][mb + lg + 8];
                Ab[mi][0] = v0.x; Asm[mi][0] = v0.y;
                Ab[mi][1] = v1.x; Asm[mi][1] = v1.y;
                Ab[mi][2] = v2.x; Asm[mi][2] = v2.y;
                Ab[mi][3] = v3.x; Asm[mi][3] = v3.y;
            }
            unsigned Bb[4][2], Bsm[4][2];
#pragma unroll
            for (int ni = 0; ni < 4; ni++) {
                uint2 w0 = SB[kb + lt]    [n0 + ni*8 + lg];
                uint2 w1 = SB[kb + lt + 4][n0 + ni*8 + lg];
                Bb[ni][0] = w0.x; Bsm[ni][0] = w0.y;
                Bb[ni][1] = w1.x; Bsm[ni][1] = w1.y;
            }
#pragma unroll
            for (int mi = 0; mi < 2; mi++)
#pragma unroll
                for (int ni = 0; ni < 4; ni++) {
                    mma_tf32(c[mi][ni], Asm[mi][0], Asm[mi][1], Asm[mi][2], Asm[mi][3],
                             Bb[ni][0], Bb[ni][1]);
                    mma_tf32(c[mi][ni], Ab[mi][0], Ab[mi][1], Ab[mi][2], Ab[mi][3],
                             Bsm[ni][0], Bsm[ni][1]);
                    mma_tf32(c[mi][ni], Ab[mi][0], Ab[mi][1], Ab[mi][2], Ab[mi][3],
                             Bb[ni][0], Bb[ni][1]);
                }
        }
        __syncthreads();
        if (s + 1 < NSTAGE) {
            stStage();
            __syncthreads();
        }
    }

    float* dst;
    if (mtype == 0)      dst = g_HP  + kq*RH;
    else if (mtype == 1) dst = g_HP2 + kq*RH;
    else if (mtype == 2) dst = g_CP  + kq*RH;
    else                 dst = g_P   + kq*PSZ;

#pragma unroll
    for (int mi = 0; mi < 2; mi++)
#pragma unroll
        for (int ni = 0; ni < 4; ni++) {
            int row = r0 + m0 + mi*16 + lg;
            int col = c0 + n0 + ni*8 + 2*lt;
            if (col < ncols) {
                dst[row*ncols + col]     = c[mi][ni][0];
                dst[(row+8)*ncols + col] = c[mi][ni][2];
            }
            if (col + 1 < ncols) {
                dst[row*ncols + col + 1]     = c[mi][ni][1];
                dst[(row+8)*ncols + col + 1] = c[mi][ni][3];
            }
        }
}

// ---------------- gating job (block handles batch b) ----------------
__device__ __forceinline__ void gate_job(
    int b, int t,
    const float* __restrict__ mask,
    const float* __restrict__ be1, const float* __restrict__ We2,
    const float* __restrict__ be2, const float* __restrict__ bs1,
    const float* __restrict__ Ws2, const float* __restrict__ bs2,
    const float* __restrict__ Ws1,
    float* __restrict__ out,
    float (&s_sim)[MCELLS], float (&s_usage)[MCELLS],
    float (&s_red)[8], float &s_ent)
{
    const int tid = threadIdx.x;
    const int warp = tid >> 5, lane = tid & 31;

    const float* P0 = g_P + b*900;
    const float* P1 = g_P + PSZ   + b*900;
    const float* P2 = g_P + 2*PSZ + b*900;
    const float* P3 = g_P + 3*PSZ + b*900;
    const float* wu_row = Ws1 + 900*300;

    if (tid < MCELLS) s_usage[tid] = g_usage[b*MCELLS + tid];
    __syncthreads();

    // ---- entity prob ----
    float acc = 0.f;
    for (int j = tid; j < 300; j += NTHREADS)
        acc += fmaxf(P0[j] + P1[j] + P2[j] + P3[j] + be1[j], 0.f) * We2[j];
    acc = warpSum(acc);
    if (lane == 0) s_red[warp] = acc;
    __syncthreads();
    if (tid == 0) {
        float s = 0.f;
        for (int w = 0; w < 8; w++) s += s_red[w];
        float score = s + be2[0];
        float sig = 1.f / (1.f + expf(-score));
        s_ent = sig * mask[(size_t)t*BATCH + b];
    }

    // ---- sim[m] ----
    for (int m = warp; m < MCELLS; m += 8) {
        float u = s_usage[m];
        const int ro = (b*MCELLS + m)*300;
        float a = 0.f;
        for (int j = lane; j < 300; j += 32) {
            float hp  = g_HP [ro+j] + g_HP [RH+ro+j] + g_HP [2*RH+ro+j] + g_HP [3*RH+ro+j];
            float hp2 = g_HP2[ro+j] + g_HP2[RH+ro+j] + g_HP2[2*RH+ro+j] + g_HP2[3*RH+ro+j];
            float ph  = P0[300+j] + P1[300+j] + P2[300+j] + P3[300+j];
            float pre = hp + hp2 + ph + u*wu_row[j] + bs1[j];
            a += fmaxf(pre, 0.f) * Ws2[j];
        }
        a = warpSum(a);
        if (lane == 0) s_sim[m] = a + bs2[0];
    }
    __syncthreads();

    // ---- gating (warp 0; lane = slot 0..20) ----
    if (warp == 0) {
        const unsigned FULL = 0xffffffffu;
        const int m = lane;
        const float NEG_INF = -INFINITY;
        float usg  = (m < MCELLS) ? s_usage[m] : 0.f;
        float simv = (m < MCELLS) ? s_sim[m]   : 0.f;

        float comb;
        if (m < MCELLS)       comb = (usg > 0.f) ? simv : -10000.f;
        else if (m == MCELLS) comb = 0.f;
        else                  comb = NEG_INF;
        float mx   = warpMax(comb);
        float ex   = (m <= MCELLS) ? expf(comb - mx) : 0.f;
        float esum = warpSum(ex);
        float prob = ex / esum;
        float mult = (m < MCELLS) ? ((usg > 0.f) ? 1.f : 0.f)
                                  : ((m == MCELLS) ? 1.f : 0.f);
        float maskedp = prob * mult;
        float msum = warpSum(maskedp);
        float nrm  = maskedp / (msum + EPS_V);
        float co   = s_ent * nrm;
        float ow_base = __shfl_sync(FULL, co, MCELLS);
        float indv = (m < MCELLS) ? co : 0.f;

        float s2  = (m < MCELLS) ? simv : NEG_INF;
        float mx2 = warpMax(s2);
        float e2  = (m < MCELLS) ? expf(simv - mx2) : 0.f;
        float es2 = warpSum(e2);
        float nsim = e2 / es2;

        float ow_score = (m < MCELLS)
            ? ((usg == 0.f ? nsim * 100000.f : 0.f) + (1.f - usg))
            : NEG_INF;
        float maxv = warpMax(ow_score);
        float nz   = (m < MCELLS && ow_score == maxv)
            ? jax_noise((unsigned)(((size_t)t*BATCH + b)*MCELLS + m)) : 0.f;
        float nzmax = warpMax(nz);
        unsigned ballot = __ballot_sync(FULL, (m < MCELLS) && (nz == nzmax));
        int idx = __ffs(ballot) - 1;

        float ow = (m == idx) ? ow_base : 0.f;
        float nu = fminf(1.f, ow + indv + DECAY * usg);

        float* out_ent = out;
        float* out_usg = out + (size_t)T_STEPS*BATCH;
        float* out_crf = out_usg + (size_t)T_STEPS*BATCH*MCELLS;
        float* out_ow  = out_crf + (size_t)T_STEPS*BATCH*MCELLS;
        if (m < MCELLS) {
            g_ow[b*MCELLS + m]    = ow;
            g_indv[b*MCELLS + m]  = indv;
            g_usage[b*MCELLS + m] = nu;
            size_t o = ((size_t)t*BATCH + b)*MCELLS + m;
            out_usg[o] = nu;
            out_crf[o] = indv * (1.f - EPS_V) + EPS_V;
            out_ow[o]  = ow   * (1.f - EPS_V) + EPS_V;
        }
        if (m == 0)
            out_ent[(size_t)t*BATCH + b] = s_ent * (1.f - EPS_V) + EPS_V;
    }
}

// ---------------- persistent kernel ----------------
__global__ __launch_bounds__(NTHREADS, 2) void k_persist(
    const float* __restrict__ hs, const float* __restrict__ mask,
    const float* __restrict__ We1, const float* __restrict__ be1,
    const float* __restrict__ We2, const float* __restrict__ be2,
    const float* __restrict__ Ws1, const float* __restrict__ bs1,
    const float* __restrict__ Ws2, const float* __restrict__ bs2,
    const float* __restrict__ Wu,  const float* __restrict__ bu,
    float* __restrict__ out, int nblk)
{
    __shared__ uint2 SA[16][130];
    __shared__ uint2 SB[16][66];
    __shared__ float s_sim[MCELLS], s_usage[MCELLS];
    __shared__ float s_red[8];
    __shared__ float s_ent;
    __shared__ int s_job;

    const int tid = threadIdx.x;
    unsigned target = 0;

    // ---- one-time: precompute weight tf32 splits ----
    for (int idx = blockIdx.x*NTHREADS + tid; idx < WBTOT; idx += nblk*NTHREADS) {
        float v;
        if (idx < 90000)        v = Ws1[idx];                       // Ws1[0:300] rows
        else if (idx < 180000)  v = Ws1[600*300 + (idx - 90000)];   // Ws1[600:900]
        else if (idx < 270000)  v = Wu[300*300 + (idx - 180000)];   // Wu[300:600]
        else {
            int e = idx - 270000;
            int k = e / 900, j = e - k*900;
            int role = j / 300, jc = j - role*300;
            if (role == 0)      v = We1[k*300 + jc];
            else if (role == 1) v = Ws1[(k + 300)*300 + jc];
            else                v = Wu[k*300 + jc];
        }
        uint2 o;
        split_tf32(v, o.x, o.y);
        g_WB[idx] = o;
    }
    grid_bar(target, nblk);

    for (int t = 0; t < T_STEPS; t++) {
        // ---- phase A: GEMMs (dynamic, tensor cores) ----
        for (;;) {
            if (tid == 0) s_job = (int)atomicAdd(&g_jobctr[t], 1u);
            __syncthreads();
            int job = s_job;
            __syncthreads();
            if (job >= NJOBS) break;
            gemm_job(job, t, hs, SA, SB);
        }
        grid_bar(target, nblk);

        // ---- phase B: gate (blocks 0..127) || cand precompute (rest) ----
        if (blockIdx.x < BATCH) {
            gate_job(blockIdx.x, t, mask, be1, We2, be2, bs1, Ws2, bs2,
                     Ws1, out, s_sim, s_usage, s_red, s_ent);
        } else {
            const float4* CP0 = (const float4*)g_CP;
            const float4* CP1 = (const float4*)(g_CP + RH);
            const float4* CP2 = (const float4*)(g_CP + 2*RH);
            const float4* CP3 = (const float4*)(g_CP + 3*RH);
            const float4* bu4 = (const float4*)bu;
            float4* cand4 = (float4*)g_cand;
            const int total = ROWS * 75;
            const int nb = nblk - BATCH;
            for (int idx = (blockIdx.x - BATCH)*NTHREADS + tid; idx < total;
                 idx += nb*NTHREADS) {
                int r  = idx / 75;
                int jq = idx - r*75;
                int b  = r / MCELLS;
                float4 c0 = CP0[idx], c1 = CP1[idx], c2 = CP2[idx], c3 = CP3[idx];
                int pbase = b*225 + 150 + jq;
                float4 p0 = ((const float4*)g_P)[pbase];
                float4 p1 = ((const float4*)(g_P + PSZ))[pbase];
                float4 p2 = ((const float4*)(g_P + 2*PSZ))[pbase];
                float4 p3 = ((const float4*)(g_P + 3*PSZ))[pbase];
                float4 bv = bu4[jq];
                float4 res;
                res.x = tanh_fast(c0.x+c1.x+c2.x+c3.x + p0.x+p1.x+p2.x+p3.x + bv.x);
                res.y = tanh_fast(c0.y+c1.y+c2.y+c3.y + p0.y+p1.y+p2.y+p3.y + bv.y);
                res.z = tanh_fast(c0.z+c1.z+c2.z+c3.z + p0.z+p1.z+p2.z+p3.z + bv.z);
                res.w = tanh_fast(c0.w+c1.w+c2.w+c3.w + p0.w+p1.w+p2.w+p3.w + bv.w);
                cand4[idx] = res;
            }
        }
        grid_bar(target, nblk);

        // ---- phase C: mem update (all blocks, float4) ----
        {
            const float4* hb4 = (const float4*)(hs + (size_t)t*BATCH*HDIM);
            const float4* cand4 = (const float4*)g_cand;
            float4* mem4 = (float4*)g_mem;
            const int total = ROWS * 75;
            for (int idx = blockIdx.x*NTHREADS + tid; idx < total;
                 idx += nblk*NTHREADS) {
                int r  = idx / 75;
                int jq = idx - r*75;
                int b  = r / MCELLS;
                float owv = g_ow[r], iv = g_indv[r];
                float coef = 1.f - owv - iv;
                float4 cd = cand4[idx];
                float4 h  = hb4[b*75 + jq];
                float4 mo = mem4[idx];
                float4 res;
                res.x = owv*h.x + coef*mo.x + iv*cd.x;
                res.y = owv*h.y + coef*mo.y + iv*cd.y;
                res.z = owv*h.z + coef*mo.z + iv*cd.z;
                res.w = owv*h.w + coef*mo.w + iv*cd.w;
                mem4[idx] = res;
            }
        }
        grid_bar(target, nblk);
    }
}

extern "C" void kernel_launch(void* const* d_in, const int* in_sizes, int n_in,
                              void* d_out, int out_size) {
    const float* hs   = (const float*)d_in[0];
    const float* mask = (const float*)d_in[1];
    const float* We1  = (const float*)d_in[2];
    const float* be1  = (const float*)d_in[3];
    const float* We2  = (const float*)d_in[4];
    const float* be2  = (const float*)d_in[5];
    const float* Ws1  = (const float*)d_in[6];
    const float* bs1  = (const float*)d_in[7];
    const float* Ws2  = (const float*)d_in[8];
    const float* bs2  = (const float*)d_in[9];
    const float* Wu   = (const float*)d_in[10];
    const float* bu   = (const float*)d_in[11];
    float* out = (float*)d_out;

    int smcount = 148;
    cudaDeviceGetAttribute(&smcount, cudaDevAttrMultiProcessorCount, 0);
    int nblk = 2 * smcount;

    void *pmem, *pusg, *pcnt, *pjob;
    cudaGetSymbolAddress(&pmem, g_mem);
    cudaGetSymbolAddress(&pusg, g_usage);
    cudaGetSymbolAddress(&pcnt, g_count);
    cudaGetSymbolAddress(&pjob, g_jobctr);
    cudaMemsetAsync(pmem, 0, sizeof(float)*(size_t)RH);
    cudaMemsetAsync(pusg, 0, sizeof(float)*(size_t)ROWS);
    cudaMemsetAsync(pcnt, 0, sizeof(unsigned));
    cudaMemsetAsync(pjob, 0, sizeof(unsigned)*T_STEPS);

    k_persist<<<nblk, NTHREADS>>>(hs, mask, We1, be1, We2, be2,
                                  Ws1, bs1, Ws2, bs2, Wu, bu, out, nblk);
}

// round 11
// speedup vs baseline: 1.2646x; 1.1139x over previous
#include <cuda_runtime.h>
#include <math.h>

// ---------------- problem constants ----------------
#define T_STEPS 512
#define BATCH   128
#define HDIM    300
#define MCELLS  20
#define ROWS    (BATCH*MCELLS)   // 2560
#define DECAY   0.98f
#define EPS_V   1e-8f

#define NTHREADS 256
#define NJOBS    630    // (3 matrices * 20rt*5ct + P 15ct) * 2 K-halves
#define RH       (ROWS*HDIM)
#define PSZ      (BATCH*900)
#define WBTOT    540000 // precomputed weight-split table entries

// 1 = JAX >= 0.4.30 default (threefry_partitionable)
#define THREEFRY_PARTITIONABLE 1

// ---------------- device state (no allocation anywhere) ----------------
__device__ float g_mem[RH];             // (B,M,H)
__device__ float g_usage[ROWS];         // (B,M)
__device__ float g_HPa [RH];            // mem@Ws1[0:300], K 0..160
__device__ float g_HPb [RH];            // K 160..300
__device__ float g_HP2a[RH];            // (h*mem)@Ws1[600:900] halves
__device__ float g_HP2b[RH];
__device__ float g_CPa [RH];            // mem@Wu[300:600] halves
__device__ float g_CPb [RH];
__device__ float g_Pa[PSZ];             // h@[We1|Ws1mid|Wu0] halves
__device__ float g_Pb[PSZ];
__device__ float g_cand[RH];            // tanh(CPa+CPb + P6 + bu)
__device__ float g_ow[ROWS];
__device__ float g_indv[ROWS];
__device__ uint2 g_WB[WBTOT];           // weight tf32 splits {big,small}
__device__ unsigned g_count;            // grid-barrier counter
__device__ unsigned g_jobctr[T_STEPS];  // per-step dynamic job counters

// ---------------- dynamic smem tile buffers ----------------
struct SmemT {
    uint2 SA[2][16][130];   // 128 rows (+pad), k16, double buffered
    uint2 SB[2][16][66];    // 64 cols (+pad)
};

// ---------------- software grid barrier ----------------
__device__ __forceinline__ void grid_bar(unsigned &target, int nblk) {
    __syncthreads();
    if (threadIdx.x == 0) {
        target += (unsigned)nblk;
        __threadfence();
        atomicAdd(&g_count, 1u);
        volatile unsigned* p = &g_count;
        while (*p < target) { }
        __threadfence();
    }
    __syncthreads();
}

// ---------------- JAX threefry-2x32-20 noise ----------------
__device__ __forceinline__ void tf_round(unsigned &x0, unsigned &x1, int r) {
    x0 += x1;
    x1 = (x1 << r) | (x1 >> (32 - r));
    x1 ^= x0;
}
__device__ __forceinline__ void threefry2x32(unsigned c0, unsigned c1,
                                             unsigned &o0, unsigned &o1) {
    const unsigned k0 = 0u, k1 = 42u, k2 = 0x1BD11BDAu ^ 0u ^ 42u;
    unsigned x0 = c0 + k0, x1 = c1 + k1;
    tf_round(x0,x1,13); tf_round(x0,x1,15); tf_round(x0,x1,26); tf_round(x0,x1,6);
    x0 += k1; x1 += k2 + 1u;
    tf_round(x0,x1,17); tf_round(x0,x1,29); tf_round(x0,x1,16); tf_round(x0,x1,24);
    x0 += k2; x1 += k0 + 2u;
    tf_round(x0,x1,13); tf_round(x0,x1,15); tf_round(x0,x1,26); tf_round(x0,x1,6);
    x0 += k0; x1 += k1 + 3u;
    tf_round(x0,x1,17); tf_round(x0,x1,29); tf_round(x0,x1,16); tf_round(x0,x1,24);
    x0 += k1; x1 += k2 + 4u;
    tf_round(x0,x1,13); tf_round(x0,x1,15); tf_round(x0,x1,26); tf_round(x0,x1,6);
    x0 += k2; x1 += k0 + 5u;
    o0 = x0; o1 = x1;
}
__device__ __forceinline__ float jax_noise(unsigned i) {
    unsigned bits;
#if THREEFRY_PARTITIONABLE
    unsigned o0, o1;
    threefry2x32(0u, i, o0, o1);
    bits = o0 ^ o1;
#else
    const unsigned half = (unsigned)(T_STEPS*BATCH*MCELLS) / 2u;
    unsigned o0, o1;
    if (i < half) { threefry2x32(i, i + half, o0, o1); bits = o0; }
    else          { threefry2x32(i - half, i, o0, o1); bits = o1; }
#endif
    float f = __uint_as_float((bits >> 9) | 0x3f800000u) - 1.0f;
    float u = __fadd_rn(__fmul_rn(f, 0.99f), 0.01f);
    return fmaxf(0.01f, u);
}

// ---------------- warp reductions ----------------
__device__ __forceinline__ float warpSum(float v) {
#pragma unroll
    for (int o = 16; o; o >>= 1) v += __shfl_xor_sync(0xffffffffu, v, o);
    return v;
}
__device__ __forceinline__ float warpMax(float v) {
#pragma unroll
    for (int o = 16; o; o >>= 1) v = fmaxf(v, __shfl_xor_sync(0xffffffffu, v, o));
    return v;
}

// fast tanh: abs err ~1e-6; __expf(inf)->inf gives exact saturation
__device__ __forceinline__ float tanh_fast(float x) {
    float ax = fabsf(x);
    float e  = __expf(2.0f * ax);
    float r  = 1.0f - __fdividef(2.0f, e + 1.0f);
    return copysignf(r, x);
}

// ---------------- tf32 helpers ----------------
__device__ __forceinline__ unsigned f2tf32(float x) {
    unsigned u;
    asm("cvt.rna.tf32.f32 %0, %1;" : "=r"(u) : "f"(x));
    return u;
}
__device__ __forceinline__ void split_tf32(float x, unsigned &big, unsigned &small) {
    big = f2tf32(x);
    float rem = x - __uint_as_float(big);
    small = f2tf32(rem);
}
__device__ __forceinline__ void mma_tf32(float c[4],
    unsigned a0, unsigned a1, unsigned a2, unsigned a3,
    unsigned b0, unsigned b1)
{
    asm("mma.sync.aligned.m16n8k8.row.col.f32.tf32.tf32.f32 "
        "{%0,%1,%2,%3}, {%4,%5,%6,%7}, {%8,%9}, {%0,%1,%2,%3};"
        : "+f"(c[0]), "+f"(c[1]), "+f"(c[2]), "+f"(c[3])
        : "r"(a0), "r"(a1), "r"(a2), "r"(a3), "r"(b0), "r"(b1));
}

// ---------------- GEMM tile job (tensor cores, 3xTF32, BM=128/BN=64/BK=16) ----
// 630 jobs. job<600: mtype=job/200 (0=HP 1=HP2 2=CP), e=job%200, kh=e&1,
//   e2=e>>1: r0=(e2/5)*128 (2560 rows), c0=(e2%5)*64 (300 cols).
// job>=600: P: e=job-600, kh=e&1, c0=(e>>1)*64 (900 cols, 15 tiles), r0=0.
// K-halves: kh=0 -> k[0,160) 10 stages; kh=1 -> k[160,304) 9 stages (zero-pad >=300).
__device__ __forceinline__ void gemm_job(
    int job, int t, const float* __restrict__ hs, SmemT* sm)
{
    const int tid = threadIdx.x;
    const float* hbase = hs + (size_t)t * BATCH * HDIM;

    int mtype, r0, c0, kh, ncols, wboff, wstride;
    if (job < 600) {
        mtype = job / 200;
        int e = job % 200;  kh = e & 1;  int e2 = e >> 1;
        r0 = (e2 / 5) * 128;  c0 = (e2 % 5) * 64;  ncols = 300;
        wboff = mtype * 90000; wstride = 300;
    } else {
        mtype = 3;
        int e = job - 600;  kh = e & 1;
        r0 = 0;  c0 = (e >> 1) * 64;  ncols = 900;
        wboff = 270000; wstride = 900;
    }
    const int kstart = kh ? 160 : 0;
    const int nstage = kh ? 9 : 10;

    // ---- A staging coords: 8 elems, m = (tid>>4)+i*16, k = tid&15 ----
    const int am = tid >> 4, ak = tid & 15;
    const float* aSrc = (mtype == 3) ? hbase : g_mem;
    const float* aBase = aSrc + (r0 + am) * HDIM;   // + i*16*HDIM
    int hOff[8];
#pragma unroll
    for (int i = 0; i < 8; i++)
        hOff[i] = ((r0 + am + i*16) / MCELLS) * HDIM;

    // ---- B staging coords: 4 uint2, n = tid&63, k = (tid>>6)+i*4 ----
    const int bn = tid & 63, bk = tid >> 6;
    const bool bok = (c0 + bn) < ncols;
    const uint2* wb = g_WB + wboff + (c0 + bn);

    // ---- warp tile: 8 warps = 4m x 2n, warp tile 32x32 ----
    const int warp = tid >> 5, lane = tid & 31;
    const int m0 = (warp >> 1) * 32;
    const int n0 = (warp & 1) * 32;
    const int lg = lane >> 2, lt = lane & 3;

    float c[2][4][4];
#pragma unroll
    for (int mi = 0; mi < 2; mi++)
#pragma unroll
        for (int ni = 0; ni < 4; ni++)
#pragma unroll
            for (int q = 0; q < 4; q++) c[mi][ni][q] = 0.f;

    float ra[8];
    uint2 rb[4];
    auto ldStage = [&](int s) {
        int kg = kstart + s*16 + ak;
        bool ok = (kg < 300);
#pragma unroll
        for (int i = 0; i < 8; i++)
            ra[i] = ok ? aBase[i*16*HDIM + kg] : 0.f;
        if (mtype == 1 && ok) {
#pragma unroll
            for (int i = 0; i < 8; i++)
                ra[i] *= hbase[hOff[i] + kg];
        }
#pragma unroll
        for (int i = 0; i < 4; i++) {
            int kg2 = kstart + s*16 + bk + i*4;
            rb[i] = (bok && kg2 < 300) ? wb[kg2*wstride] : make_uint2(0u, 0u);
        }
    };
    auto stStage = [&](int buf) {
#pragma unroll
        for (int i = 0; i < 8; i++) {
            uint2 v;
            split_tf32(ra[i], v.x, v.y);
            sm->SA[buf][ak][am + i*16] = v;
        }
#pragma unroll
        for (int i = 0; i < 4; i++)
            sm->SB[buf][bk + i*4][bn] = rb[i];
    };

    ldStage(0);
    stStage(0);
    __syncthreads();

    for (int s = 0; s < nstage; s++) {
        int cur = s & 1;
        if (s + 1 < nstage) ldStage(s + 1);   // LDG prefetch overlaps MMA
#pragma unroll
        for (int kk = 0; kk < 2; kk++) {
            const int kb = kk * 8;
            unsigned Ab[2][4], Asm[2][4];
#pragma unroll
            for (int mi = 0; mi < 2; mi++) {
                int mb = m0 + mi*16;
                uint2 v0 = sm->SA[cur][kb + lt]    [mb + lg];
                uint2 v1 = sm->SA[cur][kb + lt]    [mb + lg + 8];
                uint2 v2 = sm->SA[cur][kb + lt + 4][mb + lg];
                uint2 v3 = sm->SA[cur][kb + lt + 4][mb + lg + 8];
                Ab[mi][0] = v0.x; Asm[mi][0] = v0.y;
                Ab[mi][1] = v1.x; Asm[mi][1] = v1.y;
                Ab[mi][2] = v2.x; Asm[mi][2] = v2.y;
                Ab[mi][3] = v3.x; Asm[mi][3] = v3.y;
            }
            unsigned Bb[4][2], Bsm[4][2];
#pragma unroll
            for (int ni = 0; ni < 4; ni++) {
                uint2 w0 = sm->SB[cur][kb + lt]    [n0 + ni*8 + lg];
                uint2 w1 = sm->SB[cur][kb + lt + 4][n0 + ni*8 + lg];
                Bb[ni][0] = w0.x; Bsm[ni][0] = w0.y;
                Bb[ni][1] = w1.x; Bsm[ni][1] = w1.y;
            }
#pragma unroll
            for (int mi = 0; mi < 2; mi++)
#pragma unroll
                for (int ni = 0; ni < 4; ni++) {
                    mma_tf32(c[mi][ni], Asm[mi][0], Asm[mi][1], Asm[mi][2], Asm[mi][3],
                             Bb[ni][0], Bb[ni][1]);
                    mma_tf32(c[mi][ni], Ab[mi][0], Ab[mi][1], Ab[mi][2], Ab[mi][3],
                             Bsm[ni][0], Bsm[ni][1]);
                    mma_tf32(c[mi][ni], Ab[mi][0], Ab[mi][1], Ab[mi][2], Ab[mi][3],
                             Bb[ni][0], Bb[ni][1]);
                }
        }
        if (s + 1 < nstage) stStage(cur ^ 1);
        __syncthreads();
    }

    float* dst;
    if (mtype == 0)      dst = kh ? g_HPb  : g_HPa;
    else if (mtype == 1) dst = kh ? g_HP2b : g_HP2a;
    else if (mtype == 2) dst = kh ? g_CPb  : g_CPa;
    else                 dst = kh ? g_Pb   : g_Pa;

#pragma unroll
    for (int mi = 0; mi < 2; mi++)
#pragma unroll
        for (int ni = 0; ni < 4; ni++) {
            int row = r0 + m0 + mi*16 + lg;
            int col = c0 + n0 + ni*8 + 2*lt;
            if (col < ncols) {
                dst[row*ncols + col]     = c[mi][ni][0];
                dst[(row+8)*ncols + col] = c[mi][ni][2];
            }
            if (col + 1 < ncols) {
                dst[row*ncols + col + 1]     = c[mi][ni][1];
                dst[(row+8)*ncols + col + 1] = c[mi][ni][3];
            }
        }
}

// ---------------- gating job (block handles batch b) ----------------
__device__ __forceinline__ void gate_job(
    int b, int t,
    const float* __restrict__ mask,
    const float* __restrict__ be1, const float* __restrict__ We2,
    const float* __restrict__ be2, const float* __restrict__ bs1,
    const float* __restrict__ Ws2, const float* __restrict__ bs2,
    const float* __restrict__ Ws1,
    float* __restrict__ out,
    float (&s_sim)[MCELLS], float (&s_usage)[MCELLS],
    float (&s_red)[8], float &s_ent)
{
    const int tid = threadIdx.x;
    const int warp = tid >> 5, lane = tid & 31;

    const float* Pa = g_Pa + b*900;
    const float* Pb = g_Pb + b*900;
    const float* wu_row = Ws1 + 900*300;

    if (tid < MCELLS) s_usage[tid] = g_usage[b*MCELLS + tid];
    __syncthreads();

    // ---- entity prob ----
    float acc = 0.f;
    for (int j = tid; j < 300; j += NTHREADS)
        acc += fmaxf(Pa[j] + Pb[j] + be1[j], 0.f) * We2[j];
    acc = warpSum(acc);
    if (lane == 0) s_red[warp] = acc;
    __syncthreads();
    if (tid == 0) {
        float s = 0.f;
        for (int w = 0; w < 8; w++) s += s_red[w];
        float score = s + be2[0];
        float sig = 1.f / (1.f + expf(-score));
        s_ent = sig * mask[(size_t)t*BATCH + b];
    }

    // ---- sim[m] ----
    for (int m = warp; m < MCELLS; m += 8) {
        float u = s_usage[m];
        const int ro = (b*MCELLS + m)*300;
        float a = 0.f;
        for (int j = lane; j < 300; j += 32) {
            float pre = g_HPa[ro+j] + g_HPb[ro+j] + g_HP2a[ro+j] + g_HP2b[ro+j]
                      + Pa[300 + j] + Pb[300 + j] + u*wu_row[j] + bs1[j];
            a += fmaxf(pre, 0.f) * Ws2[j];
        }
        a = warpSum(a);
        if (lane == 0) s_sim[m] = a + bs2[0];
    }
    __syncthreads();

    // ---- gating (warp 0; lane = slot 0..20) ----
    if (warp == 0) {
        const unsigned FULL = 0xffffffffu;
        const int m = lane;
        const float NEG_INF = -INFINITY;
        float usg  = (m < MCELLS) ? s_usage[m] : 0.f;
        float simv = (m < MCELLS) ? s_sim[m]   : 0.f;

        float comb;
        if (m < MCELLS)       comb = (usg > 0.f) ? simv : -10000.f;
        else if (m == MCELLS) comb = 0.f;
        else                  comb = NEG_INF;
        float mx   = warpMax(comb);
        float ex   = (m <= MCELLS) ? expf(comb - mx) : 0.f;
        float esum = warpSum(ex);
        float prob = ex / esum;
        float mult = (m < MCELLS) ? ((usg > 0.f) ? 1.f : 0.f)
                                  : ((m == MCELLS) ? 1.f : 0.f);
        float maskedp = prob * mult;
        float msum = warpSum(maskedp);
        float nrm  = maskedp / (msum + EPS_V);
        float co   = s_ent * nrm;
        float ow_base = __shfl_sync(FULL, co, MCELLS);
        float indv = (m < MCELLS) ? co : 0.f;

        float s2  = (m < MCELLS) ? simv : NEG_INF;
        float mx2 = warpMax(s2);
        float e2  = (m < MCELLS) ? expf(simv - mx2) : 0.f;
        float es2 = warpSum(e2);
        float nsim = e2 / es2;

        float ow_score = (m < MCELLS)
            ? ((usg == 0.f ? nsim * 100000.f : 0.f) + (1.f - usg))
            : NEG_INF;
        float maxv = warpMax(ow_score);
        float nz   = (m < MCELLS && ow_score == maxv)
            ? jax_noise((unsigned)(((size_t)t*BATCH + b)*MCELLS + m)) : 0.f;
        float nzmax = warpMax(nz);
        unsigned ballot = __ballot_sync(FULL, (m < MCELLS) && (nz == nzmax));
        int idx = __ffs(ballot) - 1;

        float ow = (m == idx) ? ow_base : 0.f;
        float nu = fminf(1.f, ow + indv + DECAY * usg);

        float* out_ent = out;
        float* out_usg = out + (size_t)T_STEPS*BATCH;
        float* out_crf = out_usg + (size_t)T_STEPS*BATCH*MCELLS;
        float* out_ow  = out_crf + (size_t)T_STEPS*BATCH*MCELLS;
        if (m < MCELLS) {
            g_ow[b*MCELLS + m]    = ow;
            g_indv[b*MCELLS + m]  = indv;
            g_usage[b*MCELLS + m] = nu;
            size_t o = ((size_t)t*BATCH + b)*MCELLS + m;
            out_usg[o] = nu;
            out_crf[o] = indv * (1.f - EPS_V) + EPS_V;
            out_ow[o]  = ow   * (1.f - EPS_V) + EPS_V;
        }
        if (m == 0)
            out_ent[(size_t)t*BATCH + b] = s_ent * (1.f - EPS_V) + EPS_V;
    }
}

// ---------------- persistent kernel ----------------
__global__ __launch_bounds__(NTHREADS, 2) void k_persist(
    const float* __restrict__ hs, const float* __restrict__ mask,
    const float* __restrict__ We1, const float* __restrict__ be1,
    const float* __restrict__ We2, const float* __restrict__ be2,
    const float* __restrict__ Ws1, const float* __restrict__ bs1,
    const float* __restrict__ Ws2, const float* __restrict__ bs2,
    const float* __restrict__ Wu,  const float* __restrict__ bu,
    float* __restrict__ out, int nblk)
{
    extern __shared__ char smem_raw[];
    SmemT* sm = (SmemT*)smem_raw;

    __shared__ float s_sim[MCELLS], s_usage[MCELLS];
    __shared__ float s_red[8];
    __shared__ float s_ent;
    __shared__ int s_job;

    const int tid = threadIdx.x;
    unsigned target = 0;

    // ---- one-time: precompute weight tf32 splits ----
    for (int idx = blockIdx.x*NTHREADS + tid; idx < WBTOT; idx += nblk*NTHREADS) {
        float v;
        if (idx < 90000)        v = Ws1[idx];                       // Ws1[0:300] rows
        else if (idx < 180000)  v = Ws1[600*300 + (idx - 90000)];   // Ws1[600:900]
        else if (idx < 270000)  v = Wu[300*300 + (idx - 180000)];   // Wu[300:600]
        else {
            int e = idx - 270000;
            int k = e / 900, j = e - k*900;
            int role = j / 300, jc = j - role*300;
            if (role == 0)      v = We1[k*300 + jc];
            else if (role == 1) v = Ws1[(k + 300)*300 + jc];
            else                v = Wu[k*300 + jc];
        }
        uint2 o;
        split_tf32(v, o.x, o.y);
        g_WB[idx] = o;
    }
    grid_bar(target, nblk);

    for (int t = 0; t < T_STEPS; t++) {
        // ---- phase A: GEMMs (dynamic, tensor cores) ----
        for (;;) {
            if (tid == 0) s_job = (int)atomicAdd(&g_jobctr[t], 1u);
            __syncthreads();
            int job = s_job;
            __syncthreads();
            if (job >= NJOBS) break;
            gemm_job(job, t, hs, sm);
        }
        grid_bar(target, nblk);

        // ---- phase B: gate (blocks 0..127) || cand precompute (rest) ----
        if (blockIdx.x < BATCH) {
            gate_job(blockIdx.x, t, mask, be1, We2, be2, bs1, Ws2, bs2,
                     Ws1, out, s_sim, s_usage, s_red, s_ent);
        } else {
            const float4* CPa4 = (const float4*)g_CPa;
            const float4* CPb4 = (const float4*)g_CPb;
            const float4* Pa4  = (const float4*)g_Pa;
            const float4* Pb4  = (const float4*)g_Pb;
            const float4* bu4  = (const float4*)bu;
            float4* cand4 = (float4*)g_cand;
            const int total = ROWS * 75;
            const int nb = nblk - BATCH;
            for (int idx = (blockIdx.x - BATCH)*NTHREADS + tid; idx < total;
                 idx += nb*NTHREADS) {
                int r  = idx / 75;
                int jq = idx - r*75;
                int b  = r / MCELLS;
                float4 ca = CPa4[idx], cb = CPb4[idx];
                int pbase = b*225 + 150 + jq;
                float4 pa = Pa4[pbase], pb = Pb4[pbase];
                float4 bv = bu4[jq];
                float4 res;
                res.x = tanh_fast(ca.x + cb.x + pa.x + pb.x + bv.x);
                res.y = tanh_fast(ca.y + cb.y + pa.y + pb.y + bv.y);
                res.z = tanh_fast(ca.z + cb.z + pa.z + pb.z + bv.z);
                res.w = tanh_fast(ca.w + cb.w + pa.w + pb.w + bv.w);
                cand4[idx] = res;
            }
        }
        grid_bar(target, nblk);

        // ---- phase C: mem update (all blocks, float4) ----
        {
            const float4* hb4 = (const float4*)(hs + (size_t)t*BATCH*HDIM);
            const float4* cand4 = (const float4*)g_cand;
            float4* mem4 = (float4*)g_mem;
            const int total = ROWS * 75;
            for (int idx = blockIdx.x*NTHREADS + tid; idx < total;
                 idx += nblk*NTHREADS) {
                int r  = idx / 75;
                int jq = idx - r*75;
                int b  = r / MCELLS;
                float owv = g_ow[r], iv = g_indv[r];
                float coef = 1.f - owv - iv;
                float4 cd = cand4[idx];
                float4 h  = hb4[b*75 + jq];
                float4 mo = mem4[idx];
                float4 res;
                res.x = owv*h.x + coef*mo.x + iv*cd.x;
                res.y = owv*h.y + coef*mo.y + iv*cd.y;
                res.z = owv*h.z + coef*mo.z + iv*cd.z;
                res.w = owv*h.w + coef*mo.w + iv*cd.w;
                mem4[idx] = res;
            }
        }
        grid_bar(target, nblk);
    }
}

extern "C" void kernel_launch(void* const* d_in, const int* in_sizes, int n_in,
                              void* d_out, int out_size) {
    const float* hs   = (const float*)d_in[0];
    const float* mask = (const float*)d_in[1];
    const float* We1  = (const float*)d_in[2];
    const float* be1  = (const float*)d_in[3];
    const float* We2  = (const float*)d_in[4];
    const float* be2  = (const float*)d_in[5];
    const float* Ws1  = (const float*)d_in[6];
    const float* bs1  = (const float*)d_in[7];
    const float* Ws2  = (const float*)d_in[8];
    const float* bs2  = (const float*)d_in[9];
    const float* Wu   = (const float*)d_in[10];
    const float* bu   = (const float*)d_in[11];
    float* out = (float*)d_out;

    const int smemsz = (int)sizeof(SmemT);
    cudaFuncSetAttribute(k_persist, cudaFuncAttributeMaxDynamicSharedMemorySize,
                         smemsz);

    int smcount = 148;
    cudaDeviceGetAttribute(&smcount, cudaDevAttrMultiProcessorCount, 0);
    int maxb = 1;
    cudaOccupancyMaxActiveBlocksPerMultiprocessor(&maxb, k_persist, NTHREADS,
                                                  smemsz);
    if (maxb > 2) maxb = 2;
    if (maxb < 1) maxb = 1;
    int nblk = maxb * smcount;

    void *pmem, *pusg, *pcnt, *pjob;
    cudaGetSymbolAddress(&pmem, g_mem);
    cudaGetSymbolAddress(&pusg, g_usage);
    cudaGetSymbolAddress(&pcnt, g_count);
    cudaGetSymbolAddress(&pjob, g_jobctr);
    cudaMemsetAsync(pmem, 0, sizeof(float)*(size_t)RH);
    cudaMemsetAsync(pusg, 0, sizeof(float)*(size_t)ROWS);
    cudaMemsetAsync(pcnt, 0, sizeof(unsigned));
    cudaMemsetAsync(pjob, 0, sizeof(unsigned)*T_STEPS);

    k_persist<<<nblk, NTHREADS, smemsz>>>(hs, mask, We1, be1, We2, be2,
                                          Ws1, bs1, Ws2, bs2, Wu, bu, out, nblk);
}

// round 12
// speedup vs baseline: 1.3906x; 1.0996x over previous
#include <cuda_runtime.h>
#include <math.h>

// ---------------- problem constants ----------------
#define T_STEPS 512
#define BATCH   128
#define HDIM    300
#define MCELLS  20
#define ROWS    (BATCH*MCELLS)   // 2560
#define DECAY   0.98f
#define EPS_V   1e-8f

#define NTHREADS 256
#define NJOBS    600    // 3 matrices * 20rt*5ct * 2 K-halves  (P hoisted out)
#define PJOBS    (T_STEPS*15)   // one-time P precompute jobs
#define RH       (ROWS*HDIM)
#define PSZ      (BATCH*900)
#define WBTOT    540000 // precomputed weight-split table entries

// 1 = JAX >= 0.4.30 default (threefry_partitionable)
#define THREEFRY_PARTITIONABLE 1

// ---------------- device state (no allocation anywhere) ----------------
__device__ float g_mem[RH];             // (B,M,H)
__device__ float g_usage[ROWS];         // (B,M)
__device__ float g_HPa [RH];            // mem@Ws1[0:300], K 0..160
__device__ float g_HPb [RH];            // K 160..300
__device__ float g_HP2a[RH];            // (h*mem)@Ws1[600:900] halves
__device__ float g_HP2b[RH];
__device__ float g_CPa [RH];            // mem@Wu[300:600] halves
__device__ float g_CPb [RH];
__device__ float g_Pall[(size_t)T_STEPS*PSZ];  // h_t@[We1|Ws1mid|Wu0] all steps
__device__ float g_cand[RH];            // tanh(CPa+CPb + P6 + bu)
__device__ float g_ow[ROWS];
__device__ float g_indv[ROWS];
__device__ uint2 g_WB[WBTOT];           // weight tf32 splits {big,small}
__device__ unsigned g_count;            // grid-barrier counter
__device__ unsigned g_pctr;             // one-time P job counter
__device__ unsigned g_jobctr[T_STEPS];  // per-step dynamic job counters

// ---------------- dynamic smem tile buffers ----------------
struct SmemT {
    uint2 SA[2][16][130];   // 128 rows (+pad), k16, double buffered
    uint2 SB[2][16][66];    // 64 cols (+pad)
};

// ---------------- software grid barrier ----------------
__device__ __forceinline__ void grid_bar(unsigned &target, int nblk) {
    __syncthreads();
    if (threadIdx.x == 0) {
        target += (unsigned)nblk;
        __threadfence();
        atomicAdd(&g_count, 1u);
        volatile unsigned* p = &g_count;
        while (*p < target) { }
        __threadfence();
    }
    __syncthreads();
}

// ---------------- JAX threefry-2x32-20 noise ----------------
__device__ __forceinline__ void tf_round(unsigned &x0, unsigned &x1, int r) {
    x0 += x1;
    x1 = (x1 << r) | (x1 >> (32 - r));
    x1 ^= x0;
}
__device__ __forceinline__ void threefry2x32(unsigned c0, unsigned c1,
                                             unsigned &o0, unsigned &o1) {
    const unsigned k0 = 0u, k1 = 42u, k2 = 0x1BD11BDAu ^ 0u ^ 42u;
    unsigned x0 = c0 + k0, x1 = c1 + k1;
    tf_round(x0,x1,13); tf_round(x0,x1,15); tf_round(x0,x1,26); tf_round(x0,x1,6);
    x0 += k1; x1 += k2 + 1u;
    tf_round(x0,x1,17); tf_round(x0,x1,29); tf_round(x0,x1,16); tf_round(x0,x1,24);
    x0 += k2; x1 += k0 + 2u;
    tf_round(x0,x1,13); tf_round(x0,x1,15); tf_round(x0,x1,26); tf_round(x0,x1,6);
    x0 += k0; x1 += k1 + 3u;
    tf_round(x0,x1,17); tf_round(x0,x1,29); tf_round(x0,x1,16); tf_round(x0,x1,24);
    x0 += k1; x1 += k2 + 4u;
    tf_round(x0,x1,13); tf_round(x0,x1,15); tf_round(x0,x1,26); tf_round(x0,x1,6);
    x0 += k2; x1 += k0 + 5u;
    o0 = x0; o1 = x1;
}
__device__ __forceinline__ float jax_noise(unsigned i) {
    unsigned bits;
#if THREEFRY_PARTITIONABLE
    unsigned o0, o1;
    threefry2x32(0u, i, o0, o1);
    bits = o0 ^ o1;
#else
    const unsigned half = (unsigned)(T_STEPS*BATCH*MCELLS) / 2u;
    unsigned o0, o1;
    if (i < half) { threefry2x32(i, i + half, o0, o1); bits = o0; }
    else          { threefry2x32(i - half, i, o0, o1); bits = o1; }
#endif
    float f = __uint_as_float((bits >> 9) | 0x3f800000u) - 1.0f;
    float u = __fadd_rn(__fmul_rn(f, 0.99f), 0.01f);
    return fmaxf(0.01f, u);
}

// ---------------- warp reductions ----------------
__device__ __forceinline__ float warpSum(float v) {
#pragma unroll
    for (int o = 16; o; o >>= 1) v += __shfl_xor_sync(0xffffffffu, v, o);
    return v;
}
__device__ __forceinline__ float warpMax(float v) {
#pragma unroll
    for (int o = 16; o; o >>= 1) v = fmaxf(v, __shfl_xor_sync(0xffffffffu, v, o));
    return v;
}

// fast tanh: abs err ~1e-6; __expf(inf)->inf gives exact saturation
__device__ __forceinline__ float tanh_fast(float x) {
    float ax = fabsf(x);
    float e  = __expf(2.0f * ax);
    float r  = 1.0f - __fdividef(2.0f, e + 1.0f);
    return copysignf(r, x);
}

// ---------------- tf32 helpers ----------------
__device__ __forceinline__ unsigned f2tf32(float x) {
    unsigned u;
    asm("cvt.rna.tf32.f32 %0, %1;" : "=r"(u) : "f"(x));
    return u;
}
__device__ __forceinline__ void split_tf32(float x, unsigned &big, unsigned &small) {
    big = f2tf32(x);
    float rem = x - __uint_as_float(big);
    small = f2tf32(rem);
}
__device__ __forceinline__ void mma_tf32(float c[4],
    unsigned a0, unsigned a1, unsigned a2, unsigned a3,
    unsigned b0, unsigned b1)
{
    asm("mma.sync.aligned.m16n8k8.row.col.f32.tf32.tf32.f32 "
        "{%0,%1,%2,%3}, {%4,%5,%6,%7}, {%8,%9}, {%0,%1,%2,%3};"
        : "+f"(c[0]), "+f"(c[1]), "+f"(c[2]), "+f"(c[3])
        : "r"(a0), "r"(a1), "r"(a2), "r"(a3), "r"(b0), "r"(b1));
}

// ---------------- shared GEMM core (BM=128, BN=64, BK=16, 3xTF32) ----------------
// aRow0/aRow1: this thread's two A-row bases (+kg indexes K).
// h0/h1: elementwise multipliers (mtype==1) or nullptr.
// wb: split-weight column base (wb[k*wstride]); bok: column in range.
// dst: output tile base (row-major, stride ncols), rows r0loc.., cols c0..
__device__ __forceinline__ void gemm_core(
    const float* aRow0, const float* aRow1,
    const float* h0, const float* h1, bool domul,
    const uint2* __restrict__ wb, bool bok, int wstride,
    int kstart, int nstage,
    float* dst, int ncols, int c0, SmemT* sm)
{
    const int tid = threadIdx.x;
    const int ar0 = tid >> 2, aq4 = (tid & 3) * 4;  // row, k-quad offset
    const int bn = tid & 63, bk = tid >> 6;

    const int warp = tid >> 5, lane = tid & 31;
    const int m0 = (warp >> 1) * 32;
    const int n0 = (warp & 1) * 32;
    const int lg = lane >> 2, lt = lane & 3;

    float c[2][4][4];
#pragma unroll
    for (int mi = 0; mi < 2; mi++)
#pragma unroll
        for (int ni = 0; ni < 4; ni++)
#pragma unroll
            for (int q = 0; q < 4; q++) c[mi][ni][q] = 0.f;

    float4 ra0, ra1;
    uint2 rb[4];
    auto ldStage = [&](int s) {
        int kg = kstart + s*16 + aq4;
        if (kg < 300) {
            ra0 = *(const float4*)(aRow0 + kg);
            ra1 = *(const float4*)(aRow1 + kg);
            if (domul) {
                float4 f0 = *(const float4*)(h0 + kg);
                float4 f1 = *(const float4*)(h1 + kg);
                ra0.x *= f0.x; ra0.y *= f0.y; ra0.z *= f0.z; ra0.w *= f0.w;
                ra1.x *= f1.x; ra1.y *= f1.y; ra1.z *= f1.z; ra1.w *= f1.w;
            }
        } else {
            ra0 = make_float4(0.f,0.f,0.f,0.f);
            ra1 = make_float4(0.f,0.f,0.f,0.f);
        }
#pragma unroll
        for (int i = 0; i < 4; i++) {
            int kg2 = kstart + s*16 + bk + i*4;
            rb[i] = (bok && kg2 < 300) ? wb[kg2*wstride] : make_uint2(0u, 0u);
        }
    };
    auto stStage = [&](int buf) {
        uint2 v;
        split_tf32(ra0.x, v.x, v.y); sm->SA[buf][aq4+0][ar0] = v;
        split_tf32(ra0.y, v.x, v.y); sm->SA[buf][aq4+1][ar0] = v;
        split_tf32(ra0.z, v.x, v.y); sm->SA[buf][aq4+2][ar0] = v;
        split_tf32(ra0.w, v.x, v.y); sm->SA[buf][aq4+3][ar0] = v;
        split_tf32(ra1.x, v.x, v.y); sm->SA[buf][aq4+0][ar0+64] = v;
        split_tf32(ra1.y, v.x, v.y); sm->SA[buf][aq4+1][ar0+64] = v;
        split_tf32(ra1.z, v.x, v.y); sm->SA[buf][aq4+2][ar0+64] = v;
        split_tf32(ra1.w, v.x, v.y); sm->SA[buf][aq4+3][ar0+64] = v;
#pragma unroll
        for (int i = 0; i < 4; i++)
            sm->SB[buf][bk + i*4][bn] = rb[i];
    };

    ldStage(0);
    stStage(0);
    __syncthreads();

    for (int s = 0; s < nstage; s++) {
        int cur = s & 1;
        if (s + 1 < nstage) ldStage(s + 1);   // LDG prefetch overlaps MMA
#pragma unroll
        for (int kk = 0; kk < 2; kk++) {
            const int kb = kk * 8;
            unsigned Ab[2][4], Asm[2][4];
#pragma unroll
            for (int mi = 0; mi < 2; mi++) {
                int mb = m0 + mi*16;
                uint2 v0 = sm->SA[cur][kb + lt]    [mb + lg];
                uint2 v1 = sm->SA[cur][kb + lt]    [mb + lg + 8];
                uint2 v2 = sm->SA[cur][kb + lt + 4][mb + lg];
                uint2 v3 = sm->SA[cur][kb + lt + 4][mb + lg + 8];
                Ab[mi][0] = v0.x; Asm[mi][0] = v0.y;
                Ab[mi][1] = v1.x; Asm[mi][1] = v1.y;
                Ab[mi][2] = v2.x; Asm[mi][2] = v2.y;
                Ab[mi][3] = v3.x; Asm[mi][3] = v3.y;
            }
            unsigned Bb[4][2], Bsm[4][2];
#pragma unroll
            for (int ni = 0; ni < 4; ni++) {
                uint2 w0 = sm->SB[cur][kb + lt]    [n0 + ni*8 + lg];
                uint2 w1 = sm->SB[cur][kb + lt + 4][n0 + ni*8 + lg];
                Bb[ni][0] = w0.x; Bsm[ni][0] = w0.y;
                Bb[ni][1] = w1.x; Bsm[ni][1] = w1.y;
            }
#pragma unroll
            for (int mi = 0; mi < 2; mi++)
#pragma unroll
                for (int ni = 0; ni < 4; ni++) {
                    mma_tf32(c[mi][ni], Asm[mi][0], Asm[mi][1], Asm[mi][2], Asm[mi][3],
                             Bb[ni][0], Bb[ni][1]);
                    mma_tf32(c[mi][ni], Ab[mi][0], Ab[mi][1], Ab[mi][2], Ab[mi][3],
                             Bsm[ni][0], Bsm[ni][1]);
                    mma_tf32(c[mi][ni], Ab[mi][0], Ab[mi][1], Ab[mi][2], Ab[mi][3],
                             Bb[ni][0], Bb[ni][1]);
                }
        }
        if (s + 1 < nstage) stStage(cur ^ 1);
        __syncthreads();
    }

#pragma unroll
    for (int mi = 0; mi < 2; mi++)
#pragma unroll
        for (int ni = 0; ni < 4; ni++) {
            int row = m0 + mi*16 + lg;
            int col = c0 + n0 + ni*8 + 2*lt;
            if (col < ncols) {
                dst[row*ncols + col]     = c[mi][ni][0];
                dst[(row+8)*ncols + col] = c[mi][ni][2];
            }
            if (col + 1 < ncols) {
                dst[row*ncols + col + 1]     = c[mi][ni][1];
                dst[(row+8)*ncols + col + 1] = c[mi][ni][3];
            }
        }
}

// ---------------- per-step GEMM job (mem-dependent matrices only) ----------------
// 600 jobs: mtype=job/200 (0=HP 1=HP2 2=CP), e=job%200, kh=e&1,
//   e2=e>>1: r0=(e2/5)*128, c0=(e2%5)*64.
__device__ __forceinline__ void gemm_job(
    int job, int t, const float* __restrict__ hs, SmemT* sm)
{
    const int tid = threadIdx.x;
    const float* hbase = hs + (size_t)t * BATCH * HDIM;

    const int mtype = job / 200;
    int e = job % 200;  const int kh = e & 1;  int e2 = e >> 1;
    const int r0 = (e2 / 5) * 128, c0 = (e2 % 5) * 64;
    const int kstart = kh ? 160 : 0;
    const int nstage = kh ? 9 : 10;

    const int ar0 = tid >> 2;
    const float* aRow0 = g_mem + (r0 + ar0) * HDIM;
    const float* aRow1 = g_mem + (r0 + ar0 + 64) * HDIM;
    const float* h0 = hbase + ((r0 + ar0) / MCELLS) * HDIM;
    const float* h1 = hbase + ((r0 + ar0 + 64) / MCELLS) * HDIM;

    const int bn = tid & 63;
    const bool bok = (c0 + bn) < 300;
    const uint2* wb = g_WB + mtype * 90000 + (c0 + bn);

    float* dstbase;
    if (mtype == 0)      dstbase = kh ? g_HPb  : g_HPa;
    else if (mtype == 1) dstbase = kh ? g_HP2b : g_HP2a;
    else                 dstbase = kh ? g_CPb  : g_CPa;

    gemm_core(aRow0, aRow1, h0, h1, (mtype == 1), wb, bok, 300,
              kstart, nstage, dstbase + r0*300, 300, c0, sm);
}

// ---------------- one-time P GEMM job ----------------
// PJOBS jobs: t = job/15, c0 = (job%15)*64; rows = batch of step t; K=300.
__device__ __forceinline__ void pgemm_job(
    int job, const float* __restrict__ hs, SmemT* sm)
{
    const int tid = threadIdx.x;
    const int t = job / 15;
    const int c0 = (job % 15) * 64;
    const float* hbase = hs + (size_t)t * BATCH * HDIM;

    const int ar0 = tid >> 2;
    const float* aRow0 = hbase + ar0 * HDIM;
    const float* aRow1 = hbase + (ar0 + 64) * HDIM;

    const int bn = tid & 63;
    const bool bok = (c0 + bn) < 900;
    const uint2* wb = g_WB + 270000 + (c0 + bn);

    gemm_core(aRow0, aRow1, (const float*)0, (const float*)0, false,
              wb, bok, 900, 0, 19,
              g_Pall + (size_t)t*PSZ, 900, c0, sm);
}

// ---------------- gating job (block handles batch b) ----------------
__device__ __forceinline__ void gate_job(
    int b, int t,
    const float* __restrict__ mask,
    const float* __restrict__ be1, const float* __restrict__ We2,
    const float* __restrict__ be2, const float* __restrict__ bs1,
    const float* __restrict__ Ws2, const float* __restrict__ bs2,
    const float* __restrict__ Ws1,
    float* __restrict__ out,
    float (&s_sim)[MCELLS], float (&s_usage)[MCELLS],
    float (&s_red)[8], float &s_ent)
{
    const int tid = threadIdx.x;
    const int warp = tid >> 5, lane = tid & 31;

    const float* P = g_Pall + (size_t)t*PSZ + b*900;
    const float* wu_row = Ws1 + 900*300;

    if (tid < MCELLS) s_usage[tid] = g_usage[b*MCELLS + tid];
    __syncthreads();

    // ---- entity prob ----
    float acc = 0.f;
    for (int j = tid; j < 300; j += NTHREADS)
        acc += fmaxf(P[j] + be1[j], 0.f) * We2[j];
    acc = warpSum(acc);
    if (lane == 0) s_red[warp] = acc;
    __syncthreads();
    if (tid == 0) {
        float s = 0.f;
        for (int w = 0; w < 8; w++) s += s_red[w];
        float score = s + be2[0];
        float sig = 1.f / (1.f + expf(-score));
        s_ent = sig * mask[(size_t)t*BATCH + b];
    }

    // ---- sim[m] ----
    for (int m = warp; m < MCELLS; m += 8) {
        float u = s_usage[m];
        const int ro = (b*MCELLS + m)*300;
        float a = 0.f;
        for (int j = lane; j < 300; j += 32) {
            float pre = g_HPa[ro+j] + g_HPb[ro+j] + g_HP2a[ro+j] + g_HP2b[ro+j]
                      + P[300 + j] + u*wu_row[j] + bs1[j];
            a += fmaxf(pre, 0.f) * Ws2[j];
        }
        a = warpSum(a);
        if (lane == 0) s_sim[m] = a + bs2[0];
    }
    __syncthreads();

    // ---- gating (warp 0; lane = slot 0..20) ----
    if (warp == 0) {
        const unsigned FULL = 0xffffffffu;
        const int m = lane;
        const float NEG_INF = -INFINITY;
        float usg  = (m < MCELLS) ? s_usage[m] : 0.f;
        float simv = (m < MCELLS) ? s_sim[m]   : 0.f;

        float comb;
        if (m < MCELLS)       comb = (usg > 0.f) ? simv : -10000.f;
        else if (m == MCELLS) comb = 0.f;
        else                  comb = NEG_INF;
        float mx   = warpMax(comb);
        float ex   = (m <= MCELLS) ? expf(comb - mx) : 0.f;
        float esum = warpSum(ex);
        float prob = ex / esum;
        float mult = (m < MCELLS) ? ((usg > 0.f) ? 1.f : 0.f)
                                  : ((m == MCELLS) ? 1.f : 0.f);
        float maskedp = prob * mult;
        float msum = warpSum(maskedp);
        float nrm  = maskedp / (msum + EPS_V);
        float co   = s_ent * nrm;
        float ow_base = __shfl_sync(FULL, co, MCELLS);
        float indv = (m < MCELLS) ? co : 0.f;

        float s2  = (m < MCELLS) ? simv : NEG_INF;
        float mx2 = warpMax(s2);
        float e2  = (m < MCELLS) ? expf(simv - mx2) : 0.f;
        float es2 = warpSum(e2);
        float nsim = e2 / es2;

        float ow_score = (m < MCELLS)
            ? ((usg == 0.f ? nsim * 100000.f : 0.f) + (1.f - usg))
            : NEG_INF;
        float maxv = warpMax(ow_score);
        float nz   = (m < MCELLS && ow_score == maxv)
            ? jax_noise((unsigned)(((size_t)t*BATCH + b)*MCELLS + m)) : 0.f;
        float nzmax = warpMax(nz);
        unsigned ballot = __ballot_sync(FULL, (m < MCELLS) && (nz == nzmax));
        int idx = __ffs(ballot) - 1;

        float ow = (m == idx) ? ow_base : 0.f;
        float nu = fminf(1.f, ow + indv + DECAY * usg);

        float* out_ent = out;
        float* out_usg = out + (size_t)T_STEPS*BATCH;
        float* out_crf = out_usg + (size_t)T_STEPS*BATCH*MCELLS;
        float* out_ow  = out_crf + (size_t)T_STEPS*BATCH*MCELLS;
        if (m < MCELLS) {
            g_ow[b*MCELLS + m]    = ow;
            g_indv[b*MCELLS + m]  = indv;
            g_usage[b*MCELLS + m] = nu;
            size_t o = ((size_t)t*BATCH + b)*MCELLS + m;
            out_usg[o] = nu;
            out_crf[o] = indv * (1.f - EPS_V) + EPS_V;
            out_ow[o]  = ow   * (1.f - EPS_V) + EPS_V;
        }
        if (m == 0)
            out_ent[(size_t)t*BATCH + b] = s_ent * (1.f - EPS_V) + EPS_V;
    }
}

// ---------------- persistent kernel ----------------
__global__ __launch_bounds__(NTHREADS, 2) void k_persist(
    const float* __restrict__ hs, const float* __restrict__ mask,
    const float* __restrict__ We1, const float* __restrict__ be1,
    const float* __restrict__ We2, const float* __restrict__ be2,
    const float* __restrict__ Ws1, const float* __restrict__ bs1,
    const float* __restrict__ Ws2, const float* __restrict__ bs2,
    const float* __restrict__ Wu,  const float* __restrict__ bu,
    float* __restrict__ out, int nblk)
{
    extern __shared__ char smem_raw[];
    SmemT* sm = (SmemT*)smem_raw;

    __shared__ float s_sim[MCELLS], s_usage[MCELLS];
    __shared__ float s_red[8];
    __shared__ float s_ent;
    __shared__ int s_job;

    const int tid = threadIdx.x;
    unsigned target = 0;

    // ---- one-time: precompute weight tf32 splits ----
    for (int idx = blockIdx.x*NTHREADS + tid; idx < WBTOT; idx += nblk*NTHREADS) {
        float v;
        if (idx < 90000)        v = Ws1[idx];                       // Ws1[0:300] rows
        else if (idx < 180000)  v = Ws1[600*300 + (idx - 90000)];   // Ws1[600:900]
        else if (idx < 270000)  v = Wu[300*300 + (idx - 180000)];   // Wu[300:600]
        else {
            int e = idx - 270000;
            int k = e / 900, j = e - k*900;
            int role = j / 300, jc = j - role*300;
            if (role == 0)      v = We1[k*300 + jc];
            else if (role == 1) v = Ws1[(k + 300)*300 + jc];
            else                v = Wu[k*300 + jc];
        }
        uint2 o;
        split_tf32(v, o.x, o.y);
        g_WB[idx] = o;
    }
    grid_bar(target, nblk);

    // ---- one-time: precompute P for ALL steps (h-only GEMM) ----
    for (;;) {
        if (tid == 0) s_job = (int)atomicAdd(&g_pctr, 1u);
        __syncthreads();
        int job = s_job;
        __syncthreads();
        if (job >= PJOBS) break;
        pgemm_job(job, hs, sm);
    }
    grid_bar(target, nblk);

    for (int t = 0; t < T_STEPS; t++) {
        // ---- phase A: mem-dependent GEMMs (dynamic, tensor cores) ----
        for (;;) {
            if (tid == 0) s_job = (int)atomicAdd(&g_jobctr[t], 1u);
            __syncthreads();
            int job = s_job;
            __syncthreads();
            if (job >= NJOBS) break;
            gemm_job(job, t, hs, sm);
        }
        grid_bar(target, nblk);

        // ---- phase B: gate (blocks 0..127) || cand precompute (rest) ----
        if (blockIdx.x < BATCH) {
            gate_job(blockIdx.x, t, mask, be1, We2, be2, bs1, Ws2, bs2,
                     Ws1, out, s_sim, s_usage, s_red, s_ent);
        } else {
            const float4* CPa4 = (const float4*)g_CPa;
            const float4* CPb4 = (const float4*)g_CPb;
            const float4* Pt4  = (const float4*)(g_Pall + (size_t)t*PSZ);
            const float4* bu4  = (const float4*)bu;
            float4* cand4 = (float4*)g_cand;
            const int total = ROWS * 75;
            const int nb = nblk - BATCH;
            for (int idx = (blockIdx.x - BATCH)*NTHREADS + tid; idx < total;
                 idx += nb*NTHREADS) {
                int r  = idx / 75;
                int jq = idx - r*75;
                int b  = r / MCELLS;
                float4 ca = CPa4[idx], cb = CPb4[idx];
                float4 pa = Pt4[b*225 + 150 + jq];
                float4 bv = bu4[jq];
                float4 res;
                res.x = tanh_fast(ca.x + cb.x + pa.x + bv.x);
                res.y = tanh_fast(ca.y + cb.y + pa.y + bv.y);
                res.z = tanh_fast(ca.z + cb.z + pa.z + bv.z);
                res.w = tanh_fast(ca.w + cb.w + pa.w + bv.w);
                cand4[idx] = res;
            }
        }
        grid_bar(target, nblk);

        // ---- phase C: mem update (all blocks, float4) ----
        {
            const float4* hb4 = (const float4*)(hs + (size_t)t*BATCH*HDIM);
            const float4* cand4 = (const float4*)g_cand;
            float4* mem4 = (float4*)g_mem;
            const int total = ROWS * 75;
            for (int idx = blockIdx.x*NTHREADS + tid; idx < total;
                 idx += nblk*NTHREADS) {
                int r  = idx / 75;
                int jq = idx - r*75;
                int b  = r / MCELLS;
                float owv = g_ow[r], iv = g_indv[r];
                float coef = 1.f - owv - iv;
                float4 cd = cand4[idx];
                float4 h  = hb4[b*75 + jq];
                float4 mo = mem4[idx];
                float4 res;
                res.x = owv*h.x + coef*mo.x + iv*cd.x;
                res.y = owv*h.y + coef*mo.y + iv*cd.y;
                res.z = owv*h.z + coef*mo.z + iv*cd.z;
                res.w = owv*h.w + coef*mo.w + iv*cd.w;
                mem4[idx] = res;
            }
        }
        grid_bar(target, nblk);
    }
}

extern "C" void kernel_launch(void* const* d_in, const int* in_sizes, int n_in,
                              void* d_out, int out_size) {
    const float* hs   = (const float*)d_in[0];
    const float* mask = (const float*)d_in[1];
    const float* We1  = (const float*)d_in[2];
    const float* be1  = (const float*)d_in[3];
    const float* We2  = (const float*)d_in[4];
    const float* be2  = (const float*)d_in[5];
    const float* Ws1  = (const float*)d_in[6];
    const float* bs1  = (const float*)d_in[7];
    const float* Ws2  = (const float*)d_in[8];
    const float* bs2  = (const float*)d_in[9];
    const float* Wu   = (const float*)d_in[10];
    const float* bu   = (const float*)d_in[11];
    float* out = (float*)d_out;

    const int smemsz = (int)sizeof(SmemT);
    cudaFuncSetAttribute(k_persist, cudaFuncAttributeMaxDynamicSharedMemorySize,
                         smemsz);

    int smcount = 148;
    cudaDeviceGetAttribute(&smcount, cudaDevAttrMultiProcessorCount, 0);
    int maxb = 1;
    cudaOccupancyMaxActiveBlocksPerMultiprocessor(&maxb, k_persist, NTHREADS,
                                                  smemsz);
    if (maxb > 2) maxb = 2;
    if (maxb < 1) maxb = 1;
    int nblk = maxb * smcount;

    void *pmem, *pusg, *pcnt, *pjob, *ppc;
    cudaGetSymbolAddress(&pmem, g_mem);
    cudaGetSymbolAddress(&pusg, g_usage);
    cudaGetSymbolAddress(&pcnt, g_count);
    cudaGetSymbolAddress(&pjob, g_jobctr);
    cudaGetSymbolAddress(&ppc,  g_pctr);
    cudaMemsetAsync(pmem, 0, sizeof(float)*(size_t)RH);
    cudaMemsetAsync(pusg, 0, sizeof(float)*(size_t)ROWS);
    cudaMemsetAsync(pcnt, 0, sizeof(unsigned));
    cudaMemsetAsync(ppc,  0, sizeof(unsigned));
    cudaMemsetAsync(pjob, 0, sizeof(unsigned)*T_STEPS);

    k_persist<<<nblk, NTHREADS, smemsz>>>(hs, mask, We1, be1, We2, be2,
                                          Ws1, bs1, Ws2, bs2, Wu, bu, out, nblk);
}

// round 13
// speedup vs baseline: 1.9567x; 1.4071x over previous
#include <cuda_runtime.h>
#include <cuda_bf16.h>
#include <math.h>

// ---------------- problem constants ----------------
#define T_STEPS 512
#define BATCH   128
#define HDIM    300
#define MCELLS  20
#define ROWS    (BATCH*MCELLS)   // 2560
#define DECAY   0.98f
#define EPS_V   1e-8f

#define NTHREADS 256
#define NJOBS    600    // 3 matrices * 20rt*5ct * 2 K-halves  (P hoisted out)
#define PJOBS    (T_STEPS*15)   // one-time P precompute jobs
#define RH       (ROWS*HDIM)
#define PSZ      (BATCH*900)
#define WBTOT    270000 // packed bf16-split weight table entries (k-pairs)

// 1 = JAX >= 0.4.30 default (threefry_partitionable)
#define THREEFRY_PARTITIONABLE 1

// ---------------- device state (no allocation anywhere) ----------------
__device__ float g_mem[RH];             // (B,M,H)
__device__ float g_usage[ROWS];         // (B,M)
__device__ float g_HPa [RH];            // mem@Ws1[0:300], K 0..160
__device__ float g_HPb [RH];            // K 160..300
__device__ float g_HP2a[RH];            // (h*mem)@Ws1[600:900] halves
__device__ float g_HP2b[RH];
__device__ float g_CPa [RH];            // mem@Wu[300:600] halves
__device__ float g_CPb [RH];
__device__ float g_Pall[(size_t)T_STEPS*PSZ];  // h_t@[We1|Ws1mid|Wu0] all steps
__device__ float g_cand[RH];            // tanh(CPa+CPb + P6 + bu)
__device__ float g_ow[ROWS];
__device__ float g_indv[ROWS];
__device__ uint2 g_WB[WBTOT];           // {hi bf16-pair, lo bf16-pair} per (k-pair, col)
__device__ unsigned g_count;            // grid-barrier counter
__device__ unsigned g_pctr;             // one-time P job counter
__device__ unsigned g_jobctr[T_STEPS];  // per-step dynamic job counters

// ---------------- dynamic smem tile buffers ----------------
// row stride 24 bf16 (48 B): 16 data + 8 pad -> ldmatrix conflict-free,
// 16B-aligned rows (48 = 3*16).
struct SmemT {
    unsigned short SAh[2][128][24];
    unsigned short SAl[2][128][24];
    unsigned short SBh[2][64][24];
    unsigned short SBl[2][64][24];
};

// ---------------- software grid barrier ----------------
__device__ __forceinline__ void grid_bar(unsigned &target, int nblk) {
    __syncthreads();
    if (threadIdx.x == 0) {
        target += (unsigned)nblk;
        __threadfence();
        atomicAdd(&g_count, 1u);
        volatile unsigned* p = &g_count;
        while (*p < target) { }
        __threadfence();
    }
    __syncthreads();
}

// ---------------- JAX threefry-2x32-20 noise ----------------
__device__ __forceinline__ void tf_round(unsigned &x0, unsigned &x1, int r) {
    x0 += x1;
    x1 = (x1 << r) | (x1 >> (32 - r));
    x1 ^= x0;
}
__device__ __forceinline__ void threefry2x32(unsigned c0, unsigned c1,
                                             unsigned &o0, unsigned &o1) {
    const unsigned k0 = 0u, k1 = 42u, k2 = 0x1BD11BDAu ^ 0u ^ 42u;
    unsigned x0 = c0 + k0, x1 = c1 + k1;
    tf_round(x0,x1,13); tf_round(x0,x1,15); tf_round(x0,x1,26); tf_round(x0,x1,6);
    x0 += k1; x1 += k2 + 1u;
    tf_round(x0,x1,17); tf_round(x0,x1,29); tf_round(x0,x1,16); tf_round(x0,x1,24);
    x0 += k2; x1 += k0 + 2u;
    tf_round(x0,x1,13); tf_round(x0,x1,15); tf_round(x0,x1,26); tf_round(x0,x1,6);
    x0 += k0; x1 += k1 + 3u;
    tf_round(x0,x1,17); tf_round(x0,x1,29); tf_round(x0,x1,16); tf_round(x0,x1,24);
    x0 += k1; x1 += k2 + 4u;
    tf_round(x0,x1,13); tf_round(x0,x1,15); tf_round(x0,x1,26); tf_round(x0,x1,6);
    x0 += k2; x1 += k0 + 5u;
    o0 = x0; o1 = x1;
}
__device__ __forceinline__ float jax_noise(unsigned i) {
    unsigned bits;
#if THREEFRY_PARTITIONABLE
    unsigned o0, o1;
    threefry2x32(0u, i, o0, o1);
    bits = o0 ^ o1;
#else
    const unsigned half = (unsigned)(T_STEPS*BATCH*MCELLS) / 2u;
    unsigned o0, o1;
    if (i < half) { threefry2x32(i, i + half, o0, o1); bits = o0; }
    else          { threefry2x32(i - half, i, o0, o1); bits = o1; }
#endif
    float f = __uint_as_float((bits >> 9) | 0x3f800000u) - 1.0f;
    float u = __fadd_rn(__fmul_rn(f, 0.99f), 0.01f);
    return fmaxf(0.01f, u);
}

// ---------------- warp reductions ----------------
__device__ __forceinline__ float warpSum(float v) {
#pragma unroll
    for (int o = 16; o; o >>= 1) v += __shfl_xor_sync(0xffffffffu, v, o);
    return v;
}
__device__ __forceinline__ float warpMax(float v) {
#pragma unroll
    for (int o = 16; o; o >>= 1) v = fmaxf(v, __shfl_xor_sync(0xffffffffu, v, o));
    return v;
}

// fast tanh: abs err ~1e-6; __expf(inf)->inf gives exact saturation
__device__ __forceinline__ float tanh_fast(float x) {
    float ax = fabsf(x);
    float e  = __expf(2.0f * ax);
    float r  = 1.0f - __fdividef(2.0f, e + 1.0f);
    return copysignf(r, x);
}

// ---------------- bf16 split helpers ----------------
// pack two floats as bf16x2: LOW half = even-k element, HIGH = odd-k element
__device__ __forceinline__ unsigned pack_bf16x2(float e, float o) {
    unsigned r;
    asm("cvt.rn.bf16x2.f32 %0, %1, %2;" : "=r"(r) : "f"(o), "f"(e));
    return r;
}
__device__ __forceinline__ void bsplit(float x, float &hf, float &lf) {
    __nv_bfloat16 h = __float2bfloat16(x);
    hf = __bfloat162float(h);
    lf = x - hf;
}
__device__ __forceinline__ unsigned smem_u32(const void* p) {
    return (unsigned)__cvta_generic_to_shared(p);
}
__device__ __forceinline__ void ldsm4(unsigned r[4], unsigned addr) {
    asm volatile("ldmatrix.sync.aligned.m8n8.x4.shared.b16 {%0,%1,%2,%3}, [%4];"
        : "=r"(r[0]), "=r"(r[1]), "=r"(r[2]), "=r"(r[3]) : "r"(addr));
}
__device__ __forceinline__ void mma_bf16(float c[4],
    unsigned a0, unsigned a1, unsigned a2, unsigned a3,
    unsigned b0, unsigned b1)
{
    asm("mma.sync.aligned.m16n8k16.row.col.f32.bf16.bf16.f32 "
        "{%0,%1,%2,%3}, {%4,%5,%6,%7}, {%8,%9}, {%0,%1,%2,%3};"
        : "+f"(c[0]), "+f"(c[1]), "+f"(c[2]), "+f"(c[3])
        : "r"(a0), "r"(a1), "r"(a2), "r"(a3), "r"(b0), "r"(b1));
}

// ---------------- shared GEMM core (BM=128, BN=64, BK=16, bf16 hi/lo 3-term) ----
__device__ __forceinline__ void gemm_core(
    const float* aRow0, const float* aRow1,
    const float* h0, const float* h1, bool domul,
    const uint2* __restrict__ wb, bool bok, int wstride,
    int kstart, int nstage,
    float* dst, int ncols, int c0, SmemT* sm)
{
    const int tid = threadIdx.x;
    const int ar0 = tid >> 2, aq4 = (tid & 3) * 4;  // A: rows ar0/ar0+64, k-quad
    const int bn = tid & 63, bp = tid >> 6;         // B: col, pair-group
    const int pstart = kstart >> 1;

    const int warp = tid >> 5, lane = tid & 31;
    const int m0 = (warp >> 1) * 32;
    const int n0 = (warp & 1) * 32;
    const int lg = lane >> 2, lt = lane & 3;

    // ldmatrix lane-dependent byte offsets (row stride 24 bf16 = 48 B)
    const int lrowA = (lane & 7) + ((lane & 8) ? 8 : 0);
    const int lkA   = (lane & 16) ? 8 : 0;
    unsigned aoff[2];
#pragma unroll
    for (int mi = 0; mi < 2; mi++)
        aoff[mi] = (unsigned)(((m0 + mi*16 + lrowA) * 24 + lkA) * 2);
    const int lrowB = (lane & 7) + ((lane & 16) ? 8 : 0);
    const int lkB   = (lane & 8) ? 8 : 0;
    unsigned boff[2];
#pragma unroll
    for (int nip = 0; nip < 2; nip++)
        boff[nip] = (unsigned)(((n0 + nip*16 + lrowB) * 24 + lkB) * 2);

    unsigned baseSAh[2] = { smem_u32(&sm->SAh[0][0][0]), smem_u32(&sm->SAh[1][0][0]) };
    unsigned baseSAl[2] = { smem_u32(&sm->SAl[0][0][0]), smem_u32(&sm->SAl[1][0][0]) };
    unsigned baseSBh[2] = { smem_u32(&sm->SBh[0][0][0]), smem_u32(&sm->SBh[1][0][0]) };
    unsigned baseSBl[2] = { smem_u32(&sm->SBl[0][0][0]), smem_u32(&sm->SBl[1][0][0]) };

    float c[2][4][4];
#pragma unroll
    for (int mi = 0; mi < 2; mi++)
#pragma unroll
        for (int ni = 0; ni < 4; ni++)
#pragma unroll
            for (int q = 0; q < 4; q++) c[mi][ni][q] = 0.f;

    float4 ra0, ra1;
    uint2 rb0, rb1;
    auto ldStage = [&](int s) {
        int kg = kstart + s*16 + aq4;
        if (kg < 300) {
            ra0 = *(const float4*)(aRow0 + kg);
            ra1 = *(const float4*)(aRow1 + kg);
            if (domul) {
                float4 f0 = *(const float4*)(h0 + kg);
                float4 f1 = *(const float4*)(h1 + kg);
                ra0.x *= f0.x; ra0.y *= f0.y; ra0.z *= f0.z; ra0.w *= f0.w;
                ra1.x *= f1.x; ra1.y *= f1.y; ra1.z *= f1.z; ra1.w *= f1.w;
            }
        } else {
            ra0 = make_float4(0.f,0.f,0.f,0.f);
            ra1 = make_float4(0.f,0.f,0.f,0.f);
        }
        int p0 = pstart + s*8 + bp;
        int p1 = p0 + 4;
        rb0 = (bok && p0 < 150) ? wb[p0*wstride] : make_uint2(0u,0u);
        rb1 = (bok && p1 < 150) ? wb[p1*wstride] : make_uint2(0u,0u);
    };
    auto stStage = [&](int buf) {
        float hx,lx,hy,ly,hz,lz,hw,lw;
        bsplit(ra0.x,hx,lx); bsplit(ra0.y,hy,ly);
        bsplit(ra0.z,hz,lz); bsplit(ra0.w,hw,lw);
        *(uint2*)&sm->SAh[buf][ar0][aq4] =
            make_uint2(pack_bf16x2(hx,hy), pack_bf16x2(hz,hw));
        *(uint2*)&sm->SAl[buf][ar0][aq4] =
            make_uint2(pack_bf16x2(lx,ly), pack_bf16x2(lz,lw));
        bsplit(ra1.x,hx,lx); bsplit(ra1.y,hy,ly);
        bsplit(ra1.z,hz,lz); bsplit(ra1.w,hw,lw);
        *(uint2*)&sm->SAh[buf][ar0+64][aq4] =
            make_uint2(pack_bf16x2(hx,hy), pack_bf16x2(hz,hw));
        *(uint2*)&sm->SAl[buf][ar0+64][aq4] =
            make_uint2(pack_bf16x2(lx,ly), pack_bf16x2(lz,lw));
        *(unsigned*)&sm->SBh[buf][bn][2*bp]     = rb0.x;
        *(unsigned*)&sm->SBl[buf][bn][2*bp]     = rb0.y;
        *(unsigned*)&sm->SBh[buf][bn][2*bp + 8] = rb1.x;
        *(unsigned*)&sm->SBl[buf][bn][2*bp + 8] = rb1.y;
    };

    ldStage(0);
    stStage(0);
    __syncthreads();

    for (int s = 0; s < nstage; s++) {
        int cur = s & 1;
        if (s + 1 < nstage) ldStage(s + 1);   // LDG prefetch overlaps MMA

        unsigned Ah[2][4], Al[2][4], Bh[2][4], Bl[2][4];
#pragma unroll
        for (int mi = 0; mi < 2; mi++) {
            ldsm4(Ah[mi], baseSAh[cur] + aoff[mi]);
            ldsm4(Al[mi], baseSAl[cur] + aoff[mi]);
        }
#pragma unroll
        for (int nip = 0; nip < 2; nip++) {
            ldsm4(Bh[nip], baseSBh[cur] + boff[nip]);
            ldsm4(Bl[nip], baseSBl[cur] + boff[nip]);
        }
#pragma unroll
        for (int mi = 0; mi < 2; mi++)
#pragma unroll
            for (int ni = 0; ni < 4; ni++) {
                int nip = ni >> 1, sel = (ni & 1) * 2;
                unsigned bh0 = Bh[nip][sel], bh1 = Bh[nip][sel+1];
                unsigned bl0 = Bl[nip][sel], bl1 = Bl[nip][sel+1];
                mma_bf16(c[mi][ni], Ah[mi][0], Ah[mi][1], Ah[mi][2], Ah[mi][3],
                         bh0, bh1);
                mma_bf16(c[mi][ni], Ah[mi][0], Ah[mi][1], Ah[mi][2], Ah[mi][3],
                         bl0, bl1);
                mma_bf16(c[mi][ni], Al[mi][0], Al[mi][1], Al[mi][2], Al[mi][3],
                         bh0, bh1);
            }

        if (s + 1 < nstage) stStage(cur ^ 1);
        __syncthreads();
    }

#pragma unroll
    for (int mi = 0; mi < 2; mi++)
#pragma unroll
        for (int ni = 0; ni < 4; ni++) {
            int row = m0 + mi*16 + lg;
            int col = c0 + n0 + ni*8 + 2*lt;
            if (col < ncols) {
                dst[row*ncols + col]     = c[mi][ni][0];
                dst[(row+8)*ncols + col] = c[mi][ni][2];
            }
            if (col + 1 < ncols) {
                dst[row*ncols + col + 1]     = c[mi][ni][1];
                dst[(row+8)*ncols + col + 1] = c[mi][ni][3];
            }
        }
}

// ---------------- per-step GEMM job (mem-dependent matrices only) ----------------
__device__ __forceinline__ void gemm_job(
    int job, int t, const float* __restrict__ hs, SmemT* sm)
{
    const int tid = threadIdx.x;
    const float* hbase = hs + (size_t)t * BATCH * HDIM;

    const int mtype = job / 200;
    int e = job % 200;  const int kh = e & 1;  int e2 = e >> 1;
    const int r0 = (e2 / 5) * 128, c0 = (e2 % 5) * 64;
    const int kstart = kh ? 160 : 0;
    const int nstage = kh ? 9 : 10;

    const int ar0 = tid >> 2;
    const float* aRow0 = g_mem + (r0 + ar0) * HDIM;
    const float* aRow1 = g_mem + (r0 + ar0 + 64) * HDIM;
    const float* h0 = hbase + ((r0 + ar0) / MCELLS) * HDIM;
    const float* h1 = hbase + ((r0 + ar0 + 64) / MCELLS) * HDIM;

    const int bn = tid & 63;
    const bool bok = (c0 + bn) < 300;
    const uint2* wb = g_WB + mtype * 45000 + (c0 + bn);

    float* dstbase;
    if (mtype == 0)      dstbase = kh ? g_HPb  : g_HPa;
    else if (mtype == 1) dstbase = kh ? g_HP2b : g_HP2a;
    else                 dstbase = kh ? g_CPb  : g_CPa;

    gemm_core(aRow0, aRow1, h0, h1, (mtype == 1), wb, bok, 300,
              kstart, nstage, dstbase + r0*300, 300, c0, sm);
}

// ---------------- one-time P GEMM job ----------------
__device__ __forceinline__ void pgemm_job(
    int job, const float* __restrict__ hs, SmemT* sm)
{
    const int tid = threadIdx.x;
    const int t = job / 15;
    const int c0 = (job % 15) * 64;
    const float* hbase = hs + (size_t)t * BATCH * HDIM;

    const int ar0 = tid >> 2;
    const float* aRow0 = hbase + ar0 * HDIM;
    const float* aRow1 = hbase + (ar0 + 64) * HDIM;

    const int bn = tid & 63;
    const bool bok = (c0 + bn) < 900;
    const uint2* wb = g_WB + 135000 + (c0 + bn);

    gemm_core(aRow0, aRow1, (const float*)0, (const float*)0, false,
              wb, bok, 900, 0, 19,
              g_Pall + (size_t)t*PSZ, 900, c0, sm);
}

// ---------------- gating job (block handles batch b) ----------------
__device__ __forceinline__ void gate_job(
    int b, int t,
    const float* __restrict__ mask,
    const float* __restrict__ be1, const float* __restrict__ We2,
    const float* __restrict__ be2, const float* __restrict__ bs1,
    const float* __restrict__ Ws2, const float* __restrict__ bs2,
    const float* __restrict__ Ws1,
    float* __restrict__ out,
    float (&s_sim)[MCELLS], float (&s_usage)[MCELLS],
    float (&s_red)[8], float &s_ent)
{
    const int tid = threadIdx.x;
    const int warp = tid >> 5, lane = tid & 31;

    const float* P = g_Pall + (size_t)t*PSZ + b*900;
    const float* wu_row = Ws1 + 900*300;

    if (tid < MCELLS) s_usage[tid] = g_usage[b*MCELLS + tid];
    __syncthreads();

    // ---- entity prob ----
    float acc = 0.f;
    for (int j = tid; j < 300; j += NTHREADS)
        acc += fmaxf(P[j] + be1[j], 0.f) * We2[j];
    acc = warpSum(acc);
    if (lane == 0) s_red[warp] = acc;
    __syncthreads();
    if (tid == 0) {
        float s = 0.f;
        for (int w = 0; w < 8; w++) s += s_red[w];
        float score = s + be2[0];
        float sig = 1.f / (1.f + expf(-score));
        s_ent = sig * mask[(size_t)t*BATCH + b];
    }

    // ---- sim[m] ----
    for (int m = warp; m < MCELLS; m += 8) {
        float u = s_usage[m];
        const int ro = (b*MCELLS + m)*300;
        float a = 0.f;
        for (int j = lane; j < 300; j += 32) {
            float pre = g_HPa[ro+j] + g_HPb[ro+j] + g_HP2a[ro+j] + g_HP2b[ro+j]
                      + P[300 + j] + u*wu_row[j] + bs1[j];
            a += fmaxf(pre, 0.f) * Ws2[j];
        }
        a = warpSum(a);
        if (lane == 0) s_sim[m] = a + bs2[0];
    }
    __syncthreads();

    // ---- gating (warp 0; lane = slot 0..20) ----
    if (warp == 0) {
        const unsigned FULL = 0xffffffffu;
        const int m = lane;
        const float NEG_INF = -INFINITY;
        float usg  = (m < MCELLS) ? s_usage[m] : 0.f;
        float simv = (m < MCELLS) ? s_sim[m]   : 0.f;

        float comb;
        if (m < MCELLS)       comb = (usg > 0.f) ? simv : -10000.f;
        else if (m == MCELLS) comb = 0.f;
        else                  comb = NEG_INF;
        float mx   = warpMax(comb);
        float ex   = (m <= MCELLS) ? expf(comb - mx) : 0.f;
        float esum = warpSum(ex);
        float prob = ex / esum;
        float mult = (m < MCELLS) ? ((usg > 0.f) ? 1.f : 0.f)
                                  : ((m == MCELLS) ? 1.f : 0.f);
        float maskedp = prob * mult;
        float msum = warpSum(maskedp);
        float nrm  = maskedp / (msum + EPS_V);
        float co   = s_ent * nrm;
        float ow_base = __shfl_sync(FULL, co, MCELLS);
        float indv = (m < MCELLS) ? co : 0.f;

        float s2  = (m < MCELLS) ? simv : NEG_INF;
        float mx2 = warpMax(s2);
        float e2  = (m < MCELLS) ? expf(simv - mx2) : 0.f;
        float es2 = warpSum(e2);
        float nsim = e2 / es2;

        float ow_score = (m < MCELLS)
            ? ((usg == 0.f ? nsim * 100000.f : 0.f) + (1.f - usg))
            : NEG_INF;
        float maxv = warpMax(ow_score);
        float nz   = (m < MCELLS && ow_score == maxv)
            ? jax_noise((unsigned)(((size_t)t*BATCH + b)*MCELLS + m)) : 0.f;
        float nzmax = warpMax(nz);
        unsigned ballot = __ballot_sync(FULL, (m < MCELLS) && (nz == nzmax));
        int idx = __ffs(ballot) - 1;

        float ow = (m == idx) ? ow_base : 0.f;
        float nu = fminf(1.f, ow + indv + DECAY * usg);

        float* out_ent = out;
        float* out_usg = out + (size_t)T_STEPS*BATCH;
        float* out_crf = out_usg + (size_t)T_STEPS*BATCH*MCELLS;
        float* out_ow  = out_crf + (size_t)T_STEPS*BATCH*MCELLS;
        if (m < MCELLS) {
            g_ow[b*MCELLS + m]    = ow;
            g_indv[b*MCELLS + m]  = indv;
            g_usage[b*MCELLS + m] = nu;
            size_t o = ((size_t)t*BATCH + b)*MCELLS + m;
            out_usg[o] = nu;
            out_crf[o] = indv * (1.f - EPS_V) + EPS_V;
            out_ow[o]  = ow   * (1.f - EPS_V) + EPS_V;
        }
        if (m == 0)
            out_ent[(size_t)t*BATCH + b] = s_ent * (1.f - EPS_V) + EPS_V;
    }
}

// ---------------- persistent kernel ----------------
__global__ __launch_bounds__(NTHREADS, 2) void k_persist(
    const float* __restrict__ hs, const float* __restrict__ mask,
    const float* __restrict__ We1, const float* __restrict__ be1,
    const float* __restrict__ We2, const float* __restrict__ be2,
    const float* __restrict__ Ws1, const float* __restrict__ bs1,
    const float* __restrict__ Ws2, const float* __restrict__ bs2,
    const float* __restrict__ Wu,  const float* __restrict__ bu,
    float* __restrict__ out, int nblk)
{
    extern __shared__ char smem_raw[];
    SmemT* sm = (SmemT*)smem_raw;

    __shared__ float s_sim[MCELLS], s_usage[MCELLS];
    __shared__ float s_red[8];
    __shared__ float s_ent;
    __shared__ int s_job;

    const int tid = threadIdx.x;
    unsigned target = 0;

    // ---- one-time: precompute packed bf16 split weight table ----
    for (int idx = blockIdx.x*NTHREADS + tid; idx < WBTOT; idx += nblk*NTHREADS) {
        float v0, v1;
        if (idx < 135000) {
            int mtype = idx / 45000;
            int e = idx % 45000;
            int p = e / 300, j = e % 300;
            int k0 = 2*p, k1 = 2*p + 1;
            if (mtype == 0)      { v0 = Ws1[k0*300 + j];       v1 = Ws1[k1*300 + j]; }
            else if (mtype == 1) { v0 = Ws1[(600+k0)*300 + j]; v1 = Ws1[(600+k1)*300 + j]; }
            else                 { v0 = Wu[(300+k0)*300 + j];  v1 = Wu[(300+k1)*300 + j]; }
        } else {
            int e = idx - 135000;
            int p = e / 900, j = e % 900;
            int k0 = 2*p, k1 = 2*p + 1;
            int role = j / 300, jc = j - role*300;
            if (role == 0)      { v0 = We1[k0*300 + jc];       v1 = We1[k1*300 + jc]; }
            else if (role == 1) { v0 = Ws1[(300+k0)*300 + jc]; v1 = Ws1[(300+k1)*300 + jc]; }
            else                { v0 = Wu[k0*300 + jc];        v1 = Wu[k1*300 + jc]; }
        }
        float h0,l0,h1,l1;
        bsplit(v0, h0, l0);
        bsplit(v1, h1, l1);
        uint2 o;
        o.x = pack_bf16x2(h0, h1);
        o.y = pack_bf16x2(l0, l1);
        g_WB[idx] = o;
    }
    grid_bar(target, nblk);

    // ---- one-time: precompute P for ALL steps (h-only GEMM) ----
    for (;;) {
        if (tid == 0) s_job = (int)atomicAdd(&g_pctr, 1u);
        __syncthreads();
        int job = s_job;
        __syncthreads();
        if (job >= PJOBS) break;
        pgemm_job(job, hs, sm);
    }
    grid_bar(target, nblk);

    for (int t = 0; t < T_STEPS; t++) {
        // ---- phase A: mem-dependent GEMMs (dynamic, tensor cores) ----
        for (;;) {
            if (tid == 0) s_job = (int)atomicAdd(&g_jobctr[t], 1u);
            __syncthreads();
            int job = s_job;
            __syncthreads();
            if (job >= NJOBS) break;
            gemm_job(job, t, hs, sm);
        }
        grid_bar(target, nblk);

        // ---- phase B: gate (blocks 0..127) || cand precompute (rest) ----
        if (blockIdx.x < BATCH) {
            gate_job(blockIdx.x, t, mask, be1, We2, be2, bs1, Ws2, bs2,
                     Ws1, out, s_sim, s_usage, s_red, s_ent);
        } else {
            const float4* CPa4 = (const float4*)g_CPa;
            const float4* CPb4 = (const float4*)g_CPb;
            const float4* Pt4  = (const float4*)(g_Pall + (size_t)t*PSZ);
            const float4* bu4  = (const float4*)bu;
            float4* cand4 = (float4*)g_cand;
            const int total = ROWS * 75;
            const int nb = nblk - BATCH;
            for (int idx = (blockIdx.x - BATCH)*NTHREADS + tid; idx < total;
                 idx += nb*NTHREADS) {
                int r  = idx / 75;
                int jq = idx - r*75;
                int b  = r / MCELLS;
                float4 ca = CPa4[idx], cb = CPb4[idx];
                float4 pa = Pt4[b*225 + 150 + jq];
                float4 bv = bu4[jq];
                float4 res;
                res.x = tanh_fast(ca.x + cb.x + pa.x + bv.x);
                res.y = tanh_fast(ca.y + cb.y + pa.y + bv.y);
                res.z = tanh_fast(ca.z + cb.z + pa.z + bv.z);
                res.w = tanh_fast(ca.w + cb.w + pa.w + bv.w);
                cand4[idx] = res;
            }
        }
        grid_bar(target, nblk);

        // ---- phase C: mem update (all blocks, float4) ----
        {
            const float4* hb4 = (const float4*)(hs + (size_t)t*BATCH*HDIM);
            const float4* cand4 = (const float4*)g_cand;
            float4* mem4 = (float4*)g_mem;
            const int total = ROWS * 75;
            for (int idx = blockIdx.x*NTHREADS + tid; idx < total;
                 idx += nblk*NTHREADS) {
                int r  = idx / 75;
                int jq = idx - r*75;
                int b  = r / MCELLS;
                float owv = g_ow[r], iv = g_indv[r];
                float coef = 1.f - owv - iv;
                float4 cd = cand4[idx];
                float4 h  = hb4[b*75 + jq];
                float4 mo = mem4[idx];
                float4 res;
                res.x = owv*h.x + coef*mo.x + iv*cd.x;
                res.y = owv*h.y + coef*mo.y + iv*cd.y;
                res.z = owv*h.z + coef*mo.z + iv*cd.z;
                res.w = owv*h.w + coef*mo.w + iv*cd.w;
                mem4[idx] = res;
            }
        }
        grid_bar(target, nblk);
    }
}

extern "C" void kernel_launch(void* const* d_in, const int* in_sizes, int n_in,
                              void* d_out, int out_size) {
    const float* hs   = (const float*)d_in[0];
    const float* mask = (const float*)d_in[1];
    const float* We1  = (const float*)d_in[2];
    const float* be1  = (const float*)d_in[3];
    const float* We2  = (const float*)d_in[4];
    const float* be2  = (const float*)d_in[5];
    const float* Ws1  = (const float*)d_in[6];
    const float* bs1  = (const float*)d_in[7];
    const float* Ws2  = (const float*)d_in[8];
    const float* bs2  = (const float*)d_in[9];
    const float* Wu   = (const float*)d_in[10];
    const float* bu   = (const float*)d_in[11];
    float* out = (float*)d_out;

    const int smemsz = (int)sizeof(SmemT);
    cudaFuncSetAttribute(k_persist, cudaFuncAttributeMaxDynamicSharedMemorySize,
                         smemsz);

    int smcount = 148;
    cudaDeviceGetAttribute(&smcount, cudaDevAttrMultiProcessorCount, 0);
    int maxb = 1;
    cudaOccupancyMaxActiveBlocksPerMultiprocessor(&maxb, k_persist, NTHREADS,
                                                  smemsz);
    if (maxb > 2) maxb = 2;
    if (maxb < 1) maxb = 1;
    int nblk = maxb * smcount;

    void *pmem, *pusg, *pcnt, *pjob, *ppc;
    cudaGetSymbolAddress(&pmem, g_mem);
    cudaGetSymbolAddress(&pusg, g_usage);
    cudaGetSymbolAddress(&pcnt, g_count);
    cudaGetSymbolAddress(&pjob, g_jobctr);
    cudaGetSymbolAddress(&ppc,  g_pctr);
    cudaMemsetAsync(pmem, 0, sizeof(float)*(size_t)RH);
    cudaMemsetAsync(pusg, 0, sizeof(float)*(size_t)ROWS);
    cudaMemsetAsync(pcnt, 0, sizeof(unsigned));
    cudaMemsetAsync(ppc,  0, sizeof(unsigned));
    cudaMemsetAsync(pjob, 0, sizeof(unsigned)*T_STEPS);

    k_persist<<<nblk, NTHREADS, smemsz>>>(hs, mask, We1, be1, We2, be2,
                                          Ws1, bs1, Ws2, bs2, Wu, bu, out, nblk);
}